// round 5
// baseline (speedup 1.0000x reference)
#include <cuda_runtime.h>

// Problem constants
#define Qn   2048
#define Kn   2048
#define Cin  128
#define HD   256
#define Hh   8
#define CH   32

#define SPLITK 4
#define KS     (Kn / SPLITK)   // 512 keys per block
#define TQ     32              // q rows per block
#define TK     8               // keys per smem tile

typedef unsigned long long ull;

// ---------------- scratch (__device__ globals; no allocations allowed) ----------------
__device__ __align__(16) float g_q[Qn * HD];                 // scaled q projection
__device__ __align__(16) float g_k[Kn * HD];
__device__ __align__(16) float g_v[Kn * HD];
__device__ __align__(16) float g_g[Qn * HD];                 // sigmoid gate
__device__ __align__(16) float g_o[Qn * HD];                 // merged+gated attention out
__device__ __align__(16) float g_pacc[SPLITK * Qn * Hh * CH];// split-K partial accumulators
__device__ __align__(16) float g_pm[SPLITK * Qn * Hh];       // partial max
__device__ __align__(16) float g_pl[SPLITK * Qn * Hh];       // partial sum

// ---------------- f32x2 packed-FMA helpers (FFMA2 — only reachable via PTX) -----------
__device__ __forceinline__ ull pk(float x, float y) {
    ull r; asm("mov.b64 %0, {%1, %2};" : "=l"(r) : "f"(x), "f"(y)); return r;
}
__device__ __forceinline__ void unpk(ull v, float &x, float &y) {
    asm("mov.b64 {%0, %1}, %2;" : "=f"(x), "=f"(y) : "l"(v));
}
__device__ __forceinline__ void fma2(ull &d, ull a, ull b) {
    asm("fma.rn.f32x2 %0, %1, %2, %0;" : "+l"(d) : "l"(a), "l"(b));
}
__device__ __forceinline__ void mul2(ull &d, ull a) {
    asm("mul.rn.f32x2 %0, %0, %1;" : "+l"(d) : "l"(a));
}

// ---------------- generic 64x64-tile GEMM (row-major A[MxK] @ B[KxN]) -----------------
// mode: 0 = *1/sqrt(CH), 1/2 = none, 3 = sigmoid(x + bias[col]), 4 = x + bias[col]
__device__ __forceinline__ void gemm64x64(const float* __restrict__ A,
                                          const float* __restrict__ B,
                                          const float* __restrict__ bias,
                                          float* __restrict__ C,
                                          int N, int K, int mode) {
    __shared__ float  As[64][36];      // pad 36 -> conflict-free column reads
    __shared__ float4 Bs[32][16];

    const int tid = threadIdx.x;
    const int bm = blockIdx.x, bn = blockIdx.y;
    const int tr = tid >> 4, tc = tid & 15;

    float acc[4][4];
#pragma unroll
    for (int i = 0; i < 4; i++)
#pragma unroll
        for (int j = 0; j < 4; j++) acc[i][j] = 0.f;

    for (int k0 = 0; k0 < K; k0 += 32) {
        float4 av[2], bv[2];
#pragma unroll
        for (int r = 0; r < 2; r++) {
            int id = tid + 256 * r;
            av[r] = *(const float4*)&A[(bm * 64 + (id >> 3)) * K + k0 + (id & 7) * 4];
            bv[r] = *(const float4*)&B[(k0 + (id >> 4)) * N + bn * 64 + (id & 15) * 4];
        }
        __syncthreads();
#pragma unroll
        for (int r = 0; r < 2; r++) {
            int id = tid + 256 * r;
            *(float4*)&As[id >> 3][(id & 7) * 4] = av[r];
            Bs[id >> 4][id & 15] = bv[r];
        }
        __syncthreads();
#pragma unroll
        for (int kk = 0; kk < 32; kk++) {
            float4 b = Bs[kk][tc];
#pragma unroll
            for (int i = 0; i < 4; i++) {
                float a = As[tr * 4 + i][kk];
                acc[i][0] += a * b.x; acc[i][1] += a * b.y;
                acc[i][2] += a * b.z; acc[i][3] += a * b.w;
            }
        }
        __syncthreads();
    }

#pragma unroll
    for (int i = 0; i < 4; i++) {
        int row = bm * 64 + tr * 4 + i;
        int col = bn * 64 + tc * 4;
        float4 v;
        float* pv = &v.x;
#pragma unroll
        for (int j = 0; j < 4; j++) {
            float x = acc[i][j];
            if (mode == 0)      x *= 0.17677669529663689f;                 // 1/sqrt(32)
            else if (mode == 3) x = 1.f / (1.f + __expf(-(x + bias[col + j])));
            else if (mode == 4) x = x + bias[col + j];
            pv[j] = x;
        }
        *(float4*)&C[row * N + col] = v;
    }
}

// ---------------- kernel 1: fused projections q/k/v/gate ------------------------------
__global__ __launch_bounds__(256) void proj_kernel(const float* __restrict__ qx,
                                                   const float* __restrict__ kvx,
                                                   const float* __restrict__ Wq,
                                                   const float* __restrict__ Wk,
                                                   const float* __restrict__ Wv,
                                                   const float* __restrict__ Wg,
                                                   const float* __restrict__ bg) {
    const int z = blockIdx.z;
    const float* A; const float* B; const float* bias = nullptr; float* C;
    if (z == 0)      { A = qx;  B = Wq; C = g_q; }
    else if (z == 1) { A = kvx; B = Wk; C = g_k; }
    else if (z == 2) { A = kvx; B = Wv; C = g_v; }
    else             { A = qx;  B = Wg; C = g_g; bias = bg; }
    gemm64x64(A, B, bias, C, HD, Cin, z);
}

// ---------------- kernel 2: flash attention, split-K, all heads per block -------------
// thread = (q_local, head): tid = q_local*8 + h  (256 threads)
__global__ __launch_bounds__(256) void attn_kernel(const float* __restrict__ bias,
                                                   const float* __restrict__ dist) {
    // K/V tiles, XOR-swizzled so the 8 head-lanes of a warp hit distinct bank groups
    __shared__ float4 ks4[TK][64];
    __shared__ float4 vs4[TK][64];

    const int tid = threadIdx.x;
    const int h  = tid & 7;
    const int ql = tid >> 3;
    const int q  = blockIdx.x * TQ + ql;
    const int kb0 = blockIdx.y * KS;

    // q row for this head, packed f32x2
    ull qd[16];
    {
        const float4* qp = (const float4*)(g_q + q * HD + h * CH);
#pragma unroll
        for (int j = 0; j < 8; j++) {
            float4 t = qp[j];
            qd[2 * j]     = pk(t.x, t.y);
            qd[2 * j + 1] = pk(t.z, t.w);
        }
    }

    ull oacc[16];
#pragma unroll
    for (int j = 0; j < 16; j++) oacc[j] = 0ull;
    float m = -__int_as_float(0x7f800000);  // -inf
    float l = 0.f;

    const float* bias_row = bias + (size_t)q * Kn;
    const float* dist_row = dist + (size_t)q * Kn * Hh + h;

    for (int kb = kb0; kb < kb0 + KS; kb += TK) {
        // prefetch k/v tile to regs (overlaps previous tile's compute)
        float4 kt[2], vt[2];
#pragma unroll
        for (int r = 0; r < 2; r++) {
            int id = tid + 256 * r;
            int row = id >> 6, j = id & 63;
            kt[r] = ((const float4*)g_k)[(kb + row) * 64 + j];
            vt[r] = ((const float4*)g_v)[(kb + row) * 64 + j];
        }
        // stream distance (one 32B sector per (q,k), fully consumed) + bias
        float dr[TK], br[TK];
#pragma unroll
        for (int i = 0; i < TK; i++) {
            dr[i] = dist_row[(kb + i) * Hh];
            br[i] = bias_row[kb + i];
        }
        __syncthreads();
#pragma unroll
        for (int r = 0; r < 2; r++) {
            int id = tid + 256 * r;
            int row = id >> 6, j = id & 63;
            int hh = j >> 3, c4 = j & 7;
            int col = hh * 8 + (c4 ^ hh);       // XOR swizzle
            ks4[row][col] = kt[r];
            vs4[row][col] = vt[r];
        }
        __syncthreads();

        // scores for the tile (f32x2 dot products)
        float s[TK];
#pragma unroll
        for (int i = 0; i < TK; i++) {
            ull a0 = 0ull, a1 = 0ull;
#pragma unroll
            for (int c4 = 0; c4 < 8; c4++) {
                float4 kv = ks4[i][h * 8 + (c4 ^ h)];
                fma2(a0, qd[2 * c4],     pk(kv.x, kv.y));
                fma2(a1, qd[2 * c4 + 1], pk(kv.z, kv.w));
            }
            float x0, x1, y0, y1;
            unpk(a0, x0, x1); unpk(a1, y0, y1);
            s[i] = (x0 + x1) + (y0 + y1) + br[i] + dr[i];
        }

        // online softmax: one rescale per tile
        float tm = s[0];
#pragma unroll
        for (int i = 1; i < TK; i++) tm = fmaxf(tm, s[i]);
        float nm = fmaxf(m, tm);
        float corr = __expf(m - nm);            // 0 on first tile (m = -inf)
        m = nm;
        l *= corr;
        ull c2 = pk(corr, corr);
#pragma unroll
        for (int j = 0; j < 16; j++) mul2(oacc[j], c2);

#pragma unroll
        for (int i = 0; i < TK; i++) {
            float p = __expf(s[i] - nm);
            l += p;
            ull p2 = pk(p, p);
#pragma unroll
            for (int c4 = 0; c4 < 8; c4++) {
                float4 vv = vs4[i][h * 8 + (c4 ^ h)];
                fma2(oacc[2 * c4],     p2, pk(vv.x, vv.y));
                fma2(oacc[2 * c4 + 1], p2, pk(vv.z, vv.w));
            }
        }
    }

    // write split-K partials (unnormalized acc + m + l)
    const size_t base = ((size_t)blockIdx.y * Qn + q) * Hh + h;
    ull* pa = (ull*)g_pacc + base * 16;
#pragma unroll
    for (int j = 0; j < 16; j++) pa[j] = oacc[j];
    g_pm[base] = m;
    g_pl[base] = l;
}

// ---------------- kernel 3: split-K merge + normalize + gate --------------------------
__global__ __launch_bounds__(256) void merge_kernel() {
    const int tid = threadIdx.x;
    const int h  = tid & 7;
    const int ql = tid >> 3;
    const int q  = blockIdx.x * 32 + ql;
    const int idx = q * Hh + h;

    float mj[SPLITK], lj[SPLITK];
    float M = -__int_as_float(0x7f800000);
#pragma unroll
    for (int j = 0; j < SPLITK; j++) {
        mj[j] = g_pm[j * Qn * Hh + idx];
        lj[j] = g_pl[j * Qn * Hh + idx];
        M = fmaxf(M, mj[j]);
    }
    float w[SPLITK], L = 0.f;
#pragma unroll
    for (int j = 0; j < SPLITK; j++) {
        w[j] = __expf(mj[j] - M);
        L += w[j] * lj[j];
    }
    const float inv = 1.f / L;

    const float4* gate = (const float4*)(g_g + q * HD + h * CH);
    float4* outp       = (float4*)(g_o + q * HD + h * CH);
#pragma unroll
    for (int c4 = 0; c4 < 8; c4++) {
        float4 a = make_float4(0.f, 0.f, 0.f, 0.f);
#pragma unroll
        for (int j = 0; j < SPLITK; j++) {
            const float4 pj = ((const float4*)g_pacc)[(size_t)(j * Qn * Hh + idx) * 8 + c4];
            a.x += w[j] * pj.x; a.y += w[j] * pj.y;
            a.z += w[j] * pj.z; a.w += w[j] * pj.w;
        }
        float4 g = gate[c4];
        a.x *= inv * g.x; a.y *= inv * g.y; a.z *= inv * g.z; a.w *= inv * g.w;
        outp[c4] = a;
    }
}

// ---------------- kernel 4: output projection @Wo + bo --------------------------------
__global__ __launch_bounds__(256) void out_kernel(const float* __restrict__ Wo,
                                                  const float* __restrict__ bo,
                                                  float* __restrict__ out) {
    gemm64x64(g_o, Wo, bo, out, Cin, HD, 4);
}

// ---------------- launch --------------------------------------------------------------
extern "C" void kernel_launch(void* const* d_in, const int* in_sizes, int n_in,
                              void* d_out, int out_size) {
    (void)in_sizes; (void)n_in; (void)out_size;
    const float* qx   = (const float*)d_in[0];
    const float* kvx  = (const float*)d_in[1];
    const float* bias = (const float*)d_in[2];
    const float* dist = (const float*)d_in[3];
    const float* Wq   = (const float*)d_in[4];
    const float* Wk   = (const float*)d_in[5];
    const float* Wv   = (const float*)d_in[6];
    const float* Wg   = (const float*)d_in[7];
    const float* bg   = (const float*)d_in[8];
    const float* Wo   = (const float*)d_in[9];
    const float* bo   = (const float*)d_in[10];
    float* out = (float*)d_out;

    proj_kernel<<<dim3(Qn / 64, HD / 64, 4), 256>>>(qx, kvx, Wq, Wk, Wv, Wg, bg);
    attn_kernel<<<dim3(Qn / TQ, SPLITK), 256>>>(bias, dist);
    merge_kernel<<<dim3(Qn / 32), 256>>>();
    out_kernel<<<dim3(Qn / 64, Cin / 64), 256>>>(Wo, bo, out);
}

// round 6
// speedup vs baseline: 1.0021x; 1.0021x over previous
#include <cuda_runtime.h>

// Problem constants
#define Qn   2048
#define Kn   2048
#define Cin  128
#define HD   256
#define Hh   8
#define CH   32

#define SPLITK 4
#define KS     (Kn / SPLITK)   // 512 keys per block
#define TQ     32              // q rows per block
#define TK     8               // keys per smem tile

typedef unsigned long long ull;

// ---------------- scratch (__device__ globals; no allocations allowed) ----------------
__device__ __align__(16) float g_q[Qn * HD];                 // scaled q projection
__device__ __align__(16) float g_k[Kn * HD];
__device__ __align__(16) float g_v[Kn * HD];
__device__ __align__(16) float g_g[Qn * HD];                 // sigmoid gate
__device__ __align__(16) float g_o[Qn * HD];                 // merged+gated attention out
__device__ __align__(16) float g_pacc[SPLITK * Qn * Hh * CH];// split-K partial accumulators
__device__ __align__(16) float g_pm[SPLITK * Qn * Hh];       // partial max
__device__ __align__(16) float g_pl[SPLITK * Qn * Hh];       // partial sum

// ---------------- f32x2 packed-FMA helpers (FFMA2 — only reachable via PTX) -----------
__device__ __forceinline__ ull pk(float x, float y) {
    ull r; asm("mov.b64 %0, {%1, %2};" : "=l"(r) : "f"(x), "f"(y)); return r;
}
__device__ __forceinline__ void unpk(ull v, float &x, float &y) {
    asm("mov.b64 {%0, %1}, %2;" : "=f"(x), "=f"(y) : "l"(v));
}
__device__ __forceinline__ void fma2(ull &d, ull a, ull b) {
    asm("fma.rn.f32x2 %0, %1, %2, %0;" : "+l"(d) : "l"(a), "l"(b));
}
__device__ __forceinline__ void mul2(ull &d, ull a) {
    asm("mul.rn.f32x2 %0, %0, %1;" : "+l"(d) : "l"(a));
}

// ---------------- generic 64x64-tile GEMM (row-major A[MxK] @ B[KxN]) -----------------
// mode: 0 = *1/sqrt(CH), 1/2 = none, 3 = sigmoid(x + bias[col]), 4 = x + bias[col]
__device__ __forceinline__ void gemm64x64(const float* __restrict__ A,
                                          const float* __restrict__ B,
                                          const float* __restrict__ bias,
                                          float* __restrict__ C,
                                          int N, int K, int mode) {
    __shared__ float  As[64][36];      // pad 36 -> conflict-free column reads
    __shared__ float4 Bs[32][16];

    const int tid = threadIdx.x;
    const int bm = blockIdx.x, bn = blockIdx.y;
    const int tr = tid >> 4, tc = tid & 15;

    float acc[4][4];
#pragma unroll
    for (int i = 0; i < 4; i++)
#pragma unroll
        for (int j = 0; j < 4; j++) acc[i][j] = 0.f;

    for (int k0 = 0; k0 < K; k0 += 32) {
        float4 av[2], bv[2];
#pragma unroll
        for (int r = 0; r < 2; r++) {
            int id = tid + 256 * r;
            av[r] = *(const float4*)&A[(bm * 64 + (id >> 3)) * K + k0 + (id & 7) * 4];
            bv[r] = *(const float4*)&B[(k0 + (id >> 4)) * N + bn * 64 + (id & 15) * 4];
        }
        __syncthreads();
#pragma unroll
        for (int r = 0; r < 2; r++) {
            int id = tid + 256 * r;
            *(float4*)&As[id >> 3][(id & 7) * 4] = av[r];
            Bs[id >> 4][id & 15] = bv[r];
        }
        __syncthreads();
#pragma unroll
        for (int kk = 0; kk < 32; kk++) {
            float4 b = Bs[kk][tc];
#pragma unroll
            for (int i = 0; i < 4; i++) {
                float a = As[tr * 4 + i][kk];
                acc[i][0] += a * b.x; acc[i][1] += a * b.y;
                acc[i][2] += a * b.z; acc[i][3] += a * b.w;
            }
        }
        __syncthreads();
    }

#pragma unroll
    for (int i = 0; i < 4; i++) {
        int row = bm * 64 + tr * 4 + i;
        int col = bn * 64 + tc * 4;
        float4 v;
        float* pv = &v.x;
#pragma unroll
        for (int j = 0; j < 4; j++) {
            float x = acc[i][j];
            if (mode == 0)      x *= 0.17677669529663689f;                 // 1/sqrt(32)
            else if (mode == 3) x = 1.f / (1.f + __expf(-(x + bias[col + j])));
            else if (mode == 4) x = x + bias[col + j];
            pv[j] = x;
        }
        *(float4*)&C[row * N + col] = v;
    }
}

// ---------------- kernel 1: fused projections q/k/v/gate ------------------------------
__global__ __launch_bounds__(256) void proj_kernel(const float* __restrict__ qx,
                                                   const float* __restrict__ kvx,
                                                   const float* __restrict__ Wq,
                                                   const float* __restrict__ Wk,
                                                   const float* __restrict__ Wv,
                                                   const float* __restrict__ Wg,
                                                   const float* __restrict__ bg) {
    const int z = blockIdx.z;
    const float* A; const float* B; const float* bias = nullptr; float* C;
    if (z == 0)      { A = qx;  B = Wq; C = g_q; }
    else if (z == 1) { A = kvx; B = Wk; C = g_k; }
    else if (z == 2) { A = kvx; B = Wv; C = g_v; }
    else             { A = qx;  B = Wg; C = g_g; bias = bg; }
    gemm64x64(A, B, bias, C, HD, Cin, z);
}

// ---------------- kernel 2: flash attention, split-K, all heads per block -------------
// thread = (q_local, head): tid = q_local*8 + h  (256 threads)
__global__ __launch_bounds__(256) void attn_kernel(const float* __restrict__ bias,
                                                   const float* __restrict__ dist) {
    // K/V tiles, XOR-swizzled so the 8 head-lanes of a warp hit distinct bank groups
    __shared__ float4 ks4[TK][64];
    __shared__ float4 vs4[TK][64];

    const int tid = threadIdx.x;
    const int h  = tid & 7;
    const int ql = tid >> 3;
    const int q  = blockIdx.x * TQ + ql;
    const int kb0 = blockIdx.y * KS;

    // q row for this head, packed f32x2
    ull qd[16];
    {
        const float4* qp = (const float4*)(g_q + q * HD + h * CH);
#pragma unroll
        for (int j = 0; j < 8; j++) {
            float4 t = qp[j];
            qd[2 * j]     = pk(t.x, t.y);
            qd[2 * j + 1] = pk(t.z, t.w);
        }
    }

    ull oacc[16];
#pragma unroll
    for (int j = 0; j < 16; j++) oacc[j] = 0ull;
    float m = -__int_as_float(0x7f800000);  // -inf
    float l = 0.f;

    const float* bias_row = bias + (size_t)q * Kn;
    const float* dist_row = dist + (size_t)q * Kn * Hh + h;

    for (int kb = kb0; kb < kb0 + KS; kb += TK) {
        // prefetch k/v tile to regs (overlaps previous tile's compute)
        float4 kt[2], vt[2];
#pragma unroll
        for (int r = 0; r < 2; r++) {
            int id = tid + 256 * r;
            int row = id >> 6, j = id & 63;
            kt[r] = ((const float4*)g_k)[(kb + row) * 64 + j];
            vt[r] = ((const float4*)g_v)[(kb + row) * 64 + j];
        }
        // stream distance (one 32B sector per (q,k), fully consumed) + bias
        float dr[TK], br[TK];
#pragma unroll
        for (int i = 0; i < TK; i++) {
            dr[i] = dist_row[(kb + i) * Hh];
            br[i] = bias_row[kb + i];
        }
        __syncthreads();
#pragma unroll
        for (int r = 0; r < 2; r++) {
            int id = tid + 256 * r;
            int row = id >> 6, j = id & 63;
            int hh = j >> 3, c4 = j & 7;
            int col = hh * 8 + (c4 ^ hh);       // XOR swizzle
            ks4[row][col] = kt[r];
            vs4[row][col] = vt[r];
        }
        __syncthreads();

        // scores for the tile (f32x2 dot products)
        float s[TK];
#pragma unroll
        for (int i = 0; i < TK; i++) {
            ull a0 = 0ull, a1 = 0ull;
#pragma unroll
            for (int c4 = 0; c4 < 8; c4++) {
                float4 kv = ks4[i][h * 8 + (c4 ^ h)];
                fma2(a0, qd[2 * c4],     pk(kv.x, kv.y));
                fma2(a1, qd[2 * c4 + 1], pk(kv.z, kv.w));
            }
            float x0, x1, y0, y1;
            unpk(a0, x0, x1); unpk(a1, y0, y1);
            s[i] = (x0 + x1) + (y0 + y1) + br[i] + dr[i];
        }

        // online softmax: one rescale per tile
        float tm = s[0];
#pragma unroll
        for (int i = 1; i < TK; i++) tm = fmaxf(tm, s[i]);
        float nm = fmaxf(m, tm);
        float corr = __expf(m - nm);            // 0 on first tile (m = -inf)
        m = nm;
        l *= corr;
        ull c2 = pk(corr, corr);
#pragma unroll
        for (int j = 0; j < 16; j++) mul2(oacc[j], c2);

#pragma unroll
        for (int i = 0; i < TK; i++) {
            float p = __expf(s[i] - nm);
            l += p;
            ull p2 = pk(p, p);
#pragma unroll
            for (int c4 = 0; c4 < 8; c4++) {
                float4 vv = vs4[i][h * 8 + (c4 ^ h)];
                fma2(oacc[2 * c4],     p2, pk(vv.x, vv.y));
                fma2(oacc[2 * c4 + 1], p2, pk(vv.z, vv.w));
            }
        }
    }

    // write split-K partials (unnormalized acc + m + l)
    const size_t base = ((size_t)blockIdx.y * Qn + q) * Hh + h;
    ull* pa = (ull*)g_pacc + base * 16;
#pragma unroll
    for (int j = 0; j < 16; j++) pa[j] = oacc[j];
    g_pm[base] = m;
    g_pl[base] = l;
}

// ---------------- kernel 3: split-K merge + normalize + gate --------------------------
__global__ __launch_bounds__(256) void merge_kernel() {
    const int tid = threadIdx.x;
    const int h  = tid & 7;
    const int ql = tid >> 3;
    const int q  = blockIdx.x * 32 + ql;
    const int idx = q * Hh + h;

    float mj[SPLITK], lj[SPLITK];
    float M = -__int_as_float(0x7f800000);
#pragma unroll
    for (int j = 0; j < SPLITK; j++) {
        mj[j] = g_pm[j * Qn * Hh + idx];
        lj[j] = g_pl[j * Qn * Hh + idx];
        M = fmaxf(M, mj[j]);
    }
    float w[SPLITK], L = 0.f;
#pragma unroll
    for (int j = 0; j < SPLITK; j++) {
        w[j] = __expf(mj[j] - M);
        L += w[j] * lj[j];
    }
    const float inv = 1.f / L;

    const float4* gate = (const float4*)(g_g + q * HD + h * CH);
    float4* outp       = (float4*)(g_o + q * HD + h * CH);
#pragma unroll
    for (int c4 = 0; c4 < 8; c4++) {
        float4 a = make_float4(0.f, 0.f, 0.f, 0.f);
#pragma unroll
        for (int j = 0; j < SPLITK; j++) {
            const float4 pj = ((const float4*)g_pacc)[(size_t)(j * Qn * Hh + idx) * 8 + c4];
            a.x += w[j] * pj.x; a.y += w[j] * pj.y;
            a.z += w[j] * pj.z; a.w += w[j] * pj.w;
        }
        float4 g = gate[c4];
        a.x *= inv * g.x; a.y *= inv * g.y; a.z *= inv * g.z; a.w *= inv * g.w;
        outp[c4] = a;
    }
}

// ---------------- kernel 4: output projection @Wo + bo --------------------------------
__global__ __launch_bounds__(256) void out_kernel(const float* __restrict__ Wo,
                                                  const float* __restrict__ bo,
                                                  float* __restrict__ out) {
    gemm64x64(g_o, Wo, bo, out, Cin, HD, 4);
}

// ---------------- launch --------------------------------------------------------------
extern "C" void kernel_launch(void* const* d_in, const int* in_sizes, int n_in,
                              void* d_out, int out_size) {
    (void)in_sizes; (void)n_in; (void)out_size;
    const float* qx   = (const float*)d_in[0];
    const float* kvx  = (const float*)d_in[1];
    const float* bias = (const float*)d_in[2];
    const float* dist = (const float*)d_in[3];
    const float* Wq   = (const float*)d_in[4];
    const float* Wk   = (const float*)d_in[5];
    const float* Wv   = (const float*)d_in[6];
    const float* Wg   = (const float*)d_in[7];
    const float* bg   = (const float*)d_in[8];
    const float* Wo   = (const float*)d_in[9];
    const float* bo   = (const float*)d_in[10];
    float* out = (float*)d_out;

    proj_kernel<<<dim3(Qn / 64, HD / 64, 4), 256>>>(qx, kvx, Wq, Wk, Wv, Wg, bg);
    attn_kernel<<<dim3(Qn / TQ, SPLITK), 256>>>(bias, dist);
    merge_kernel<<<dim3(Qn / 32), 256>>>();
    out_kernel<<<dim3(Qn / 64, Cin / 64), 256>>>(Wo, bo, out);
}

// round 9
// speedup vs baseline: 3.7832x; 3.7752x over previous
#include <cuda_runtime.h>
#include <cuda_fp16.h>
#include <stdint.h>

#define Qn   2048
#define Kn   2048
#define Cin  128
#define HD   256
#define Hh   8
#define CH   32

#define SPLITK 2
#define KS     (Kn / SPLITK)   // 1024 keys per block
#define KT     64              // keys per smem tile
#define TQ     16              // q rows per block

// smem layout (bytes): K [64 rows][528B] @0 ; V @33792 ; ds fp32 [8h][16q][68f] @67584
#define KROW     528
#define VS_OFF   33792
#define DS_OFF   67584
#define DS_PLANE 1088          // floats per head plane (16*68)
#define SM_BYTES 102400

// ---------------- scratch ----------------
__device__ __align__(16) __half g_qh[Qn * HD];   // q/sqrt(32)
__device__ __align__(16) __half g_kh[Kn * HD];
__device__ __align__(16) __half g_vh[Kn * HD];
__device__ __align__(16) float g_g[Qn * HD];     // sigmoid gate
__device__ __align__(16) float g_o[Qn * HD];     // merged+gated out
__device__ __align__(16) float g_pacc[SPLITK * Qn * Hh * CH];
__device__ __align__(16) float g_pm[SPLITK * Qn * Hh];
__device__ __align__(16) float g_pl[SPLITK * Qn * Hh];

// ---------------- mma helpers ----------------
__device__ __forceinline__ uint32_t smem_u32(const void* p) {
    return (uint32_t)__cvta_generic_to_shared(p);
}
__device__ __forceinline__ void ldsm_x2(uint32_t& r0, uint32_t& r1, uint32_t a) {
    asm volatile("ldmatrix.sync.aligned.m8n8.x2.shared.b16 {%0,%1},[%2];"
                 : "=r"(r0), "=r"(r1) : "r"(a));
}
__device__ __forceinline__ void ldsm_x2_t(uint32_t& r0, uint32_t& r1, uint32_t a) {
    asm volatile("ldmatrix.sync.aligned.m8n8.x2.trans.shared.b16 {%0,%1},[%2];"
                 : "=r"(r0), "=r"(r1) : "r"(a));
}
__device__ __forceinline__ void mma_f16(float* c, const uint32_t* a, uint32_t b0, uint32_t b1) {
    asm volatile("mma.sync.aligned.m16n8k16.row.col.f32.f16.f16.f32 "
                 "{%0,%1,%2,%3},{%4,%5,%6,%7},{%8,%9},{%0,%1,%2,%3};"
                 : "+f"(c[0]), "+f"(c[1]), "+f"(c[2]), "+f"(c[3])
                 : "r"(a[0]), "r"(a[1]), "r"(a[2]), "r"(a[3]), "r"(b0), "r"(b1));
}
__device__ __forceinline__ uint32_t pkhf(float lo, float hi) {
    __half2 h = __floats2half2_rn(lo, hi);
    return *reinterpret_cast<uint32_t*>(&h);
}

// ---------------- generic tiled GEMM (TM x 64 tile) ----------------
// mode: 0 q->fp16 *1/sqrt(32); 1/2 ->fp16; 3 fp32 sigmoid(x+bias); 4 fp32 x+bias
template <int TM>
__device__ __forceinline__ void gemm_tile(const float* __restrict__ A,
                                          const float* __restrict__ B,
                                          const float* __restrict__ bias,
                                          void* __restrict__ Cout,
                                          int N, int K, int mode) {
    __shared__ float  As[TM][36];
    __shared__ float4 Bs[32][16];

    const int tid = threadIdx.x;
    const int bm = blockIdx.x, bn = blockIdx.y;
    const int tr = tid >> 4, tc = tid & 15;
    constexpr int RPT = TM / 16;

    float acc[RPT][4];
#pragma unroll
    for (int i = 0; i < RPT; i++)
#pragma unroll
        for (int j = 0; j < 4; j++) acc[i][j] = 0.f;

    for (int k0 = 0; k0 < K; k0 += 32) {
        float4 av[TM / 32], bv[2];
#pragma unroll
        for (int r = 0; r < TM / 32; r++) {
            int id = tid + 256 * r;
            av[r] = *(const float4*)&A[(size_t)(bm * TM + (id >> 3)) * K + k0 + (id & 7) * 4];
        }
#pragma unroll
        for (int r = 0; r < 2; r++) {
            int id = tid + 256 * r;
            bv[r] = *(const float4*)&B[(size_t)(k0 + (id >> 4)) * N + bn * 64 + (id & 15) * 4];
        }
        __syncthreads();
#pragma unroll
        for (int r = 0; r < TM / 32; r++) {
            int id = tid + 256 * r;
            *(float4*)&As[id >> 3][(id & 7) * 4] = av[r];
        }
#pragma unroll
        for (int r = 0; r < 2; r++) {
            int id = tid + 256 * r;
            Bs[id >> 4][id & 15] = bv[r];
        }
        __syncthreads();
#pragma unroll
        for (int kk = 0; kk < 32; kk++) {
            float4 b = Bs[kk][tc];
#pragma unroll
            for (int i = 0; i < RPT; i++) {
                float a = As[tr * RPT + i][kk];
                acc[i][0] += a * b.x; acc[i][1] += a * b.y;
                acc[i][2] += a * b.z; acc[i][3] += a * b.w;
            }
        }
        __syncthreads();
    }

#pragma unroll
    for (int i = 0; i < RPT; i++) {
        int row = bm * TM + tr * RPT + i;
        int col = bn * 64 + tc * 4;
        float v[4];
#pragma unroll
        for (int j = 0; j < 4; j++) {
            float x = acc[i][j];
            if (mode == 0)      x *= 0.17677669529663689f;
            else if (mode == 3) x = 1.f / (1.f + __expf(-(x + bias[col + j])));
            else if (mode == 4) x = x + bias[col + j];
            v[j] = x;
        }
        if (mode <= 2) {
            __half2 h0 = __floats2half2_rn(v[0], v[1]);
            __half2 h1 = __floats2half2_rn(v[2], v[3]);
            uint2 p = make_uint2(*reinterpret_cast<uint32_t*>(&h0),
                                 *reinterpret_cast<uint32_t*>(&h1));
            *reinterpret_cast<uint2*>((__half*)Cout + (size_t)row * N + col) = p;
        } else {
            *(float4*)((float*)Cout + (size_t)row * N + col) =
                make_float4(v[0], v[1], v[2], v[3]);
        }
    }
}

// ---------------- kernel 1: projections ----------------
__global__ __launch_bounds__(256) void proj_kernel(const float* __restrict__ qx,
                                                   const float* __restrict__ kvx,
                                                   const float* __restrict__ Wq,
                                                   const float* __restrict__ Wk,
                                                   const float* __restrict__ Wv,
                                                   const float* __restrict__ Wg,
                                                   const float* __restrict__ bg) {
    const int z = blockIdx.z;
    const float* A; const float* B; const float* bias = nullptr; void* C;
    if (z == 0)      { A = qx;  B = Wq; C = g_qh; }
    else if (z == 1) { A = kvx; B = Wk; C = g_kh; }
    else if (z == 2) { A = kvx; B = Wv; C = g_vh; }
    else             { A = qx;  B = Wg; C = g_g; bias = bg; }
    gemm_tile<64>(A, B, bias, C, HD, Cin, z);
}

// ---------------- kernel 2: flash attention (HMMA fp16, warp = head) ----------------
__global__ __launch_bounds__(256, 2) void attn_kernel(const float* __restrict__ bias,
                                                      const float* __restrict__ dist) {
    extern __shared__ char smem[];
    const int tid  = threadIdx.x;
    const int w    = tid >> 5;       // head
    const int lane = tid & 31;
    const int q0   = blockIdx.x * TQ;
    const int sp   = blockIdx.y;
    const int kb0  = sp * KS;
    const int rq   = lane >> 2;      // 0..7
    const int c2   = (lane & 3) * 2;

    char* ksm = smem;
    char* vsm = smem + VS_OFF;
    float* dsw = (float*)(smem + DS_OFF) + w * DS_PLANE;
    const uint32_t Kb = smem_u32(smem) + w * 64;
    const uint32_t Vb = smem_u32(smem) + VS_OFF + w * 64;

    // Q A-fragments (2 k-steps over CH=32)
    uint32_t qa[2][4];
    {
        const __half* qp = g_qh + (size_t)(q0 + rq) * HD + w * CH + c2;
#pragma unroll
        for (int s = 0; s < 2; s++) {
            qa[s][0] = *(const uint32_t*)(qp + s * 16);
            qa[s][1] = *(const uint32_t*)(qp + 8 * HD + s * 16);
            qa[s][2] = *(const uint32_t*)(qp + s * 16 + 8);
            qa[s][3] = *(const uint32_t*)(qp + 8 * HD + s * 16 + 8);
        }
    }

    float o[4][4];
#pragma unroll
    for (int n = 0; n < 4; n++)
#pragma unroll
        for (int j = 0; j < 4; j++) o[n][j] = 0.f;
    const float NINF = -__int_as_float(0x7f800000);
    float m0 = NINF, m1 = NINF, l0 = 0.f, l1 = 0.f;

    for (int kb = kb0; kb < kb0 + KS; kb += KT) {
        __syncthreads();
        // stage K/V tile (64 keys x 256 ch fp16 = 512B used of 528B pitch)
#pragma unroll
        for (int r = 0; r < 8; r++) {
            int idx = tid + 256 * r;
            int row = idx >> 5, c = idx & 31;
            *(float4*)(ksm + row * KROW + c * 16) =
                ((const float4*)(g_kh + (size_t)(kb + row) * HD))[c];
            *(float4*)(vsm + row * KROW + c * 16) =
                ((const float4*)(g_vh + (size_t)(kb + row) * HD))[c];
        }
        // stage dist+bias -> per-head planes [16q][68f]
#pragma unroll
        for (int r = 0; r < 8; r++) {
            int idx = tid + 256 * r;
            int h4 = (idx & 1) * 4, k = (idx >> 1) & 63, q = idx >> 7;
            float4 d = *(const float4*)(dist + ((size_t)(q0 + q) * Kn + kb + k) * Hh + h4);
            float b = __ldg(bias + (size_t)(q0 + q) * Kn + kb + k);
            float* dp = (float*)(smem + DS_OFF) + h4 * DS_PLANE + q * 68 + k;
            dp[0]            = d.x + b;
            dp[DS_PLANE]     = d.y + b;
            dp[2 * DS_PLANE] = d.z + b;
            dp[3 * DS_PLANE] = d.w + b;
        }
        __syncthreads();

        // S = dist+bias + Q K^T   (init accumulators from ds)
        float s[8][4];
#pragma unroll
        for (int n = 0; n < 8; n++) {
            float2 t0 = *(float2*)(dsw + rq * 68 + n * 8 + c2);
            float2 t1 = *(float2*)(dsw + (rq + 8) * 68 + n * 8 + c2);
            s[n][0] = t0.x; s[n][1] = t0.y; s[n][2] = t1.x; s[n][3] = t1.y;
        }
#pragma unroll
        for (int ks = 0; ks < 2; ks++)
#pragma unroll
            for (int n = 0; n < 8; n++) {
                uint32_t b0, b1;
                ldsm_x2(b0, b1, Kb + (n * 8 + (lane & 7)) * KROW
                                  + ((lane >> 3) & 1) * 16 + ks * 32);
                mma_f16(s[n], qa[ks], b0, b1);
            }

        // online softmax
        float mx0 = NINF, mx1 = NINF;
#pragma unroll
        for (int n = 0; n < 8; n++) {
            mx0 = fmaxf(mx0, fmaxf(s[n][0], s[n][1]));
            mx1 = fmaxf(mx1, fmaxf(s[n][2], s[n][3]));
        }
        mx0 = fmaxf(mx0, __shfl_xor_sync(0xffffffffu, mx0, 1));
        mx0 = fmaxf(mx0, __shfl_xor_sync(0xffffffffu, mx0, 2));
        mx1 = fmaxf(mx1, __shfl_xor_sync(0xffffffffu, mx1, 1));
        mx1 = fmaxf(mx1, __shfl_xor_sync(0xffffffffu, mx1, 2));
        float nm0 = fmaxf(m0, mx0), nm1 = fmaxf(m1, mx1);
        float cr0 = __expf(m0 - nm0), cr1 = __expf(m1 - nm1);
        m0 = nm0; m1 = nm1;
        l0 *= cr0; l1 *= cr1;
#pragma unroll
        for (int n = 0; n < 4; n++) {
            o[n][0] *= cr0; o[n][1] *= cr0; o[n][2] *= cr1; o[n][3] *= cr1;
        }

        // P = exp(S - m), packed straight into PV A-fragments
        uint32_t pa[4][4];
        float sm0 = 0.f, sm1 = 0.f;
#pragma unroll
        for (int n = 0; n < 8; n++) {
            float p0 = __expf(s[n][0] - m0), p1 = __expf(s[n][1] - m0);
            float p2 = __expf(s[n][2] - m1), p3 = __expf(s[n][3] - m1);
            sm0 += p0 + p1; sm1 += p2 + p3;
            int j = n >> 1;
            if ((n & 1) == 0) { pa[j][0] = pkhf(p0, p1); pa[j][1] = pkhf(p2, p3); }
            else              { pa[j][2] = pkhf(p0, p1); pa[j][3] = pkhf(p2, p3); }
        }
        l0 += sm0; l1 += sm1;

        // O += P V
#pragma unroll
        for (int j = 0; j < 4; j++)
#pragma unroll
            for (int nn = 0; nn < 4; nn++) {
                uint32_t b0, b1;
                ldsm_x2_t(b0, b1, Vb + (16 * j + (lane & 15)) * KROW + nn * 16);
                mma_f16(o[nn], pa[j], b0, b1);
            }
    }

    // reduce row sums across quad
    l0 += __shfl_xor_sync(0xffffffffu, l0, 1);
    l0 += __shfl_xor_sync(0xffffffffu, l0, 2);
    l1 += __shfl_xor_sync(0xffffffffu, l1, 1);
    l1 += __shfl_xor_sync(0xffffffffu, l1, 2);

    // store split-K partials
    const size_t i0 = ((size_t)(sp * Qn + q0 + rq) * Hh + w) * CH;
    const size_t i1 = ((size_t)(sp * Qn + q0 + rq + 8) * Hh + w) * CH;
#pragma unroll
    for (int nn = 0; nn < 4; nn++) {
        *(float2*)(g_pacc + i0 + nn * 8 + c2) = make_float2(o[nn][0], o[nn][1]);
        *(float2*)(g_pacc + i1 + nn * 8 + c2) = make_float2(o[nn][2], o[nn][3]);
    }
    if ((lane & 3) == 0) {
        g_pm[(size_t)(sp * Qn + q0 + rq) * Hh + w] = m0;
        g_pl[(size_t)(sp * Qn + q0 + rq) * Hh + w] = l0;
        g_pm[(size_t)(sp * Qn + q0 + rq + 8) * Hh + w] = m1;
        g_pl[(size_t)(sp * Qn + q0 + rq + 8) * Hh + w] = l1;
    }
}

// ---------------- kernel 3: split-K merge + normalize + gate ----------------
__global__ __launch_bounds__(256) void merge_kernel() {
    const int tid = threadIdx.x;
    const int h  = tid & 7;
    const int ql = tid >> 3;
    const int q  = blockIdx.x * 32 + ql;
    const int idx = q * Hh + h;

    float mj[SPLITK], lj[SPLITK];
    float M = -__int_as_float(0x7f800000);
#pragma unroll
    for (int j = 0; j < SPLITK; j++) {
        mj[j] = g_pm[j * Qn * Hh + idx];
        lj[j] = g_pl[j * Qn * Hh + idx];
        M = fmaxf(M, mj[j]);
    }
    float w[SPLITK], L = 0.f;
#pragma unroll
    for (int j = 0; j < SPLITK; j++) {
        w[j] = __expf(mj[j] - M);
        L += w[j] * lj[j];
    }
    const float inv = 1.f / L;

    const float4* gate = (const float4*)(g_g + q * HD + h * CH);
    float4* outp       = (float4*)(g_o + q * HD + h * CH);
#pragma unroll
    for (int c4 = 0; c4 < 8; c4++) {
        float4 a = make_float4(0.f, 0.f, 0.f, 0.f);
#pragma unroll
        for (int j = 0; j < SPLITK; j++) {
            const float4 pj = ((const float4*)g_pacc)[(size_t)(j * Qn * Hh + idx) * 8 + c4];
            a.x += w[j] * pj.x; a.y += w[j] * pj.y;
            a.z += w[j] * pj.z; a.w += w[j] * pj.w;
        }
        float4 g = gate[c4];
        a.x *= inv * g.x; a.y *= inv * g.y; a.z *= inv * g.z; a.w *= inv * g.w;
        outp[c4] = a;
    }
}

// ---------------- kernel 4: output projection ----------------
__global__ __launch_bounds__(256) void out_kernel(const float* __restrict__ Wo,
                                                  const float* __restrict__ bo,
                                                  float* __restrict__ out) {
    gemm_tile<32>(g_o, Wo, bo, out, Cin, HD, 4);
}

// ---------------- launch ----------------
extern "C" void kernel_launch(void* const* d_in, const int* in_sizes, int n_in,
                              void* d_out, int out_size) {
    (void)in_sizes; (void)n_in; (void)out_size;
    const float* qx   = (const float*)d_in[0];
    const float* kvx  = (const float*)d_in[1];
    const float* bias = (const float*)d_in[2];
    const float* dist = (const float*)d_in[3];
    const float* Wq   = (const float*)d_in[4];
    const float* Wk   = (const float*)d_in[5];
    const float* Wv   = (const float*)d_in[6];
    const float* Wg   = (const float*)d_in[7];
    const float* bg   = (const float*)d_in[8];
    const float* Wo   = (const float*)d_in[9];
    const float* bo   = (const float*)d_in[10];
    float* out = (float*)d_out;

    cudaFuncSetAttribute(attn_kernel, cudaFuncAttributeMaxDynamicSharedMemorySize,
                         SM_BYTES);

    proj_kernel<<<dim3(Qn / 64, HD / 64, 4), 256>>>(qx, kvx, Wq, Wk, Wv, Wg, bg);
    attn_kernel<<<dim3(Qn / TQ, SPLITK), 256, SM_BYTES>>>(bias, dist);
    merge_kernel<<<dim3(Qn / 32), 256>>>();
    out_kernel<<<dim3(Qn / 32, Cin / 64), 256>>>(Wo, bo, out);
}

// round 10
// speedup vs baseline: 4.1376x; 1.0937x over previous
#include <cuda_runtime.h>
#include <cuda_fp16.h>
#include <stdint.h>

#define Qn   2048
#define Kn   2048
#define Cin  128
#define HD   256
#define Hh   8
#define CH   32

#define SPLITK 2
#define KS     (Kn / SPLITK)   // 1024 keys per block
#define KT     32              // keys per smem tile
#define NTILES (KS / KT)       // 32
#define TQ     16              // q rows per block

// per-buffer smem layout (bytes): K [32 rows][528B] @0 ; V @16896 ; ds fp32 [8h][16q][36f] @33792
#define KROW     528
#define VOFF     16896
#define DSOFF    33792
#define DSPLANE  576           // floats per head plane (16*36)
#define BUFB     52224
#define SM_BYTES (2 * BUFB)    // 104448

// ---------------- scratch ----------------
__device__ __align__(16) __half g_qh[Qn * HD];   // q/sqrt(32)
__device__ __align__(16) __half g_kh[Kn * HD];
__device__ __align__(16) __half g_vh[Kn * HD];
__device__ __align__(16) float g_g[Qn * HD];     // sigmoid gate
__device__ __align__(16) float g_o[Qn * HD];     // merged+gated out
__device__ __align__(16) float g_pacc[SPLITK * Qn * Hh * CH];
__device__ __align__(16) float g_pm[SPLITK * Qn * Hh];
__device__ __align__(16) float g_pl[SPLITK * Qn * Hh];

// ---------------- asm helpers ----------------
__device__ __forceinline__ uint32_t smem_u32(const void* p) {
    return (uint32_t)__cvta_generic_to_shared(p);
}
__device__ __forceinline__ void cpasync16(uint32_t dst, const void* src) {
    asm volatile("cp.async.cg.shared.global [%0], [%1], 16;" :: "r"(dst), "l"(src));
}
__device__ __forceinline__ void cp_commit() {
    asm volatile("cp.async.commit_group;");
}
template <int N>
__device__ __forceinline__ void cp_wait() {
    asm volatile("cp.async.wait_group %0;" :: "n"(N));
}
__device__ __forceinline__ void ldsm_x2(uint32_t& r0, uint32_t& r1, uint32_t a) {
    asm volatile("ldmatrix.sync.aligned.m8n8.x2.shared.b16 {%0,%1},[%2];"
                 : "=r"(r0), "=r"(r1) : "r"(a));
}
__device__ __forceinline__ void ldsm_x2_t(uint32_t& r0, uint32_t& r1, uint32_t a) {
    asm volatile("ldmatrix.sync.aligned.m8n8.x2.trans.shared.b16 {%0,%1},[%2];"
                 : "=r"(r0), "=r"(r1) : "r"(a));
}
__device__ __forceinline__ void mma_f16(float* c, const uint32_t* a, uint32_t b0, uint32_t b1) {
    asm volatile("mma.sync.aligned.m16n8k16.row.col.f32.f16.f16.f32 "
                 "{%0,%1,%2,%3},{%4,%5,%6,%7},{%8,%9},{%0,%1,%2,%3};"
                 : "+f"(c[0]), "+f"(c[1]), "+f"(c[2]), "+f"(c[3])
                 : "r"(a[0]), "r"(a[1]), "r"(a[2]), "r"(a[3]), "r"(b0), "r"(b1));
}
__device__ __forceinline__ uint32_t pkhf(float lo, float hi) {
    __half2 h = __floats2half2_rn(lo, hi);
    return *reinterpret_cast<uint32_t*>(&h);
}

// ---------------- generic tiled GEMM (TM x 64 tile) ----------------
// mode: 0 q->fp16 *1/sqrt(32); 1/2 ->fp16; 3 fp32 sigmoid(x+bias); 4 fp32 x+bias
template <int TM>
__device__ __forceinline__ void gemm_tile(const float* __restrict__ A,
                                          const float* __restrict__ B,
                                          const float* __restrict__ bias,
                                          void* __restrict__ Cout,
                                          int N, int K, int mode) {
    __shared__ float  As[TM][36];
    __shared__ float4 Bs[32][16];

    const int tid = threadIdx.x;
    const int bm = blockIdx.x, bn = blockIdx.y;
    const int tr = tid >> 4, tc = tid & 15;
    constexpr int RPT = TM / 16;
    constexpr int AN  = (TM * 8 + 255) / 256;   // A float4 loads per thread

    float acc[RPT][4];
#pragma unroll
    for (int i = 0; i < RPT; i++)
#pragma unroll
        for (int j = 0; j < 4; j++) acc[i][j] = 0.f;

    for (int k0 = 0; k0 < K; k0 += 32) {
        float4 av[AN], bv[2];
#pragma unroll
        for (int r = 0; r < AN; r++) {
            int id = tid + 256 * r;
            if (TM * 8 >= 256 || id < TM * 8)
                av[r] = *(const float4*)&A[(size_t)(bm * TM + (id >> 3)) * K + k0 + (id & 7) * 4];
        }
#pragma unroll
        for (int r = 0; r < 2; r++) {
            int id = tid + 256 * r;
            bv[r] = *(const float4*)&B[(size_t)(k0 + (id >> 4)) * N + bn * 64 + (id & 15) * 4];
        }
        __syncthreads();
#pragma unroll
        for (int r = 0; r < AN; r++) {
            int id = tid + 256 * r;
            if (TM * 8 >= 256 || id < TM * 8)
                *(float4*)&As[id >> 3][(id & 7) * 4] = av[r];
        }
#pragma unroll
        for (int r = 0; r < 2; r++) {
            int id = tid + 256 * r;
            Bs[id >> 4][id & 15] = bv[r];
        }
        __syncthreads();
#pragma unroll
        for (int kk = 0; kk < 32; kk++) {
            float4 b = Bs[kk][tc];
#pragma unroll
            for (int i = 0; i < RPT; i++) {
                float a = As[tr * RPT + i][kk];
                acc[i][0] += a * b.x; acc[i][1] += a * b.y;
                acc[i][2] += a * b.z; acc[i][3] += a * b.w;
            }
        }
        __syncthreads();
    }

#pragma unroll
    for (int i = 0; i < RPT; i++) {
        int row = bm * TM + tr * RPT + i;
        int col = bn * 64 + tc * 4;
        float v[4];
#pragma unroll
        for (int j = 0; j < 4; j++) {
            float x = acc[i][j];
            if (mode == 0)      x *= 0.17677669529663689f;
            else if (mode == 3) x = 1.f / (1.f + __expf(-(x + bias[col + j])));
            else if (mode == 4) x = x + bias[col + j];
            v[j] = x;
        }
        if (mode <= 2) {
            __half2 h0 = __floats2half2_rn(v[0], v[1]);
            __half2 h1 = __floats2half2_rn(v[2], v[3]);
            uint2 p = make_uint2(*reinterpret_cast<uint32_t*>(&h0),
                                 *reinterpret_cast<uint32_t*>(&h1));
            *reinterpret_cast<uint2*>((__half*)Cout + (size_t)row * N + col) = p;
        } else {
            *(float4*)((float*)Cout + (size_t)row * N + col) =
                make_float4(v[0], v[1], v[2], v[3]);
        }
    }
}

// ---------------- kernel 1: projections ----------------
__global__ __launch_bounds__(256) void proj_kernel(const float* __restrict__ qx,
                                                   const float* __restrict__ kvx,
                                                   const float* __restrict__ Wq,
                                                   const float* __restrict__ Wk,
                                                   const float* __restrict__ Wv,
                                                   const float* __restrict__ Wg,
                                                   const float* __restrict__ bg) {
    const int z = blockIdx.z;
    const float* A; const float* B; const float* bias = nullptr; void* C;
    if (z == 0)      { A = qx;  B = Wq; C = g_qh; }
    else if (z == 1) { A = kvx; B = Wk; C = g_kh; }
    else if (z == 2) { A = kvx; B = Wv; C = g_vh; }
    else             { A = qx;  B = Wg; C = g_g; bias = bg; }
    gemm_tile<64>(A, B, bias, C, HD, Cin, z);
}

// ---------------- kernel 2: flash attention (HMMA fp16, pipelined) ----------------
__global__ __launch_bounds__(256, 2) void attn_kernel(const float* __restrict__ bias,
                                                      const float* __restrict__ dist) {
    extern __shared__ char smem[];
    const int tid  = threadIdx.x;
    const int w    = tid >> 5;       // head
    const int lane = tid & 31;
    const int q0   = blockIdx.x * TQ;
    const int sp   = blockIdx.y;
    const int kb0  = sp * KS;
    const int rq   = lane >> 2;      // 0..7
    const int c2   = (lane & 3) * 2;

    const uint32_t sb = smem_u32(smem);

    // staging index decomposition (per r in 0..3, idx = tid + 256*r):
    //   K/V: row = idx>>5 (0..31), c = idx&31
    //   ds : h4 = (idx&1)*4, k = (idx>>1)&31, q = idx>>6

    // Q A-fragments (2 k-steps over CH=32)
    uint32_t qa[2][4];
    {
        const __half* qp = g_qh + (size_t)(q0 + rq) * HD + w * CH + c2;
#pragma unroll
        for (int s = 0; s < 2; s++) {
            qa[s][0] = *(const uint32_t*)(qp + s * 16);
            qa[s][1] = *(const uint32_t*)(qp + 8 * HD + s * 16);
            qa[s][2] = *(const uint32_t*)(qp + s * 16 + 8);
            qa[s][3] = *(const uint32_t*)(qp + 8 * HD + s * 16 + 8);
        }
    }

    float o[4][4];
#pragma unroll
    for (int n = 0; n < 4; n++)
#pragma unroll
        for (int j = 0; j < 4; j++) o[n][j] = 0.f;
    const float NINF = -__int_as_float(0x7f800000);
    float m0 = NINF, m1 = NINF, l0 = 0.f, l1 = 0.f;

    float4 dreg[4];
    float  breg[4];

    // ---- prologue: start tile 0 ----
    {
        const int kb = kb0;
#pragma unroll
        for (int r = 0; r < 4; r++) {
            int idx = tid + 256 * r;
            int row = idx >> 5, c = idx & 31;
            cpasync16(sb + row * KROW + c * 16, g_kh + (size_t)(kb + row) * HD + c * 8);
            cpasync16(sb + VOFF + row * KROW + c * 16, g_vh + (size_t)(kb + row) * HD + c * 8);
        }
        cp_commit();
#pragma unroll
        for (int r = 0; r < 4; r++) {
            int idx = tid + 256 * r;
            int h4 = (idx & 1) * 4, k = (idx >> 1) & 31, q = idx >> 6;
            dreg[r] = *(const float4*)(dist + ((size_t)(q0 + q) * Kn + kb + k) * Hh + h4);
            breg[r] = __ldg(bias + (size_t)(q0 + q) * Kn + kb + k);
        }
    }

    for (int t = 0; t < NTILES; t++) {
        const int b = t & 1;
        const uint32_t bufb = sb + b * BUFB;
        float* dsb = (float*)(smem + b * BUFB + DSOFF);

        // store dist(t)+bias into ds[b]
#pragma unroll
        for (int r = 0; r < 4; r++) {
            int idx = tid + 256 * r;
            int h4 = (idx & 1) * 4, k = (idx >> 1) & 31, q = idx >> 6;
            float* dp = dsb + h4 * DSPLANE + q * 36 + k;
            float bb = breg[r];
            dp[0]           = dreg[r].x + bb;
            dp[DSPLANE]     = dreg[r].y + bb;
            dp[2 * DSPLANE] = dreg[r].z + bb;
            dp[3 * DSPLANE] = dreg[r].w + bb;
        }

        if (t + 1 < NTILES) {
            const int kb = kb0 + (t + 1) * KT;
            const uint32_t nb = sb + (b ^ 1) * BUFB;
#pragma unroll
            for (int r = 0; r < 4; r++) {
                int idx = tid + 256 * r;
                int row = idx >> 5, c = idx & 31;
                cpasync16(nb + row * KROW + c * 16, g_kh + (size_t)(kb + row) * HD + c * 8);
                cpasync16(nb + VOFF + row * KROW + c * 16, g_vh + (size_t)(kb + row) * HD + c * 8);
            }
            cp_commit();
#pragma unroll
            for (int r = 0; r < 4; r++) {
                int idx = tid + 256 * r;
                int h4 = (idx & 1) * 4, k = (idx >> 1) & 31, q = idx >> 6;
                dreg[r] = *(const float4*)(dist + ((size_t)(q0 + q) * Kn + kb + k) * Hh + h4);
                breg[r] = __ldg(bias + (size_t)(q0 + q) * Kn + kb + k);
            }
            cp_wait<1>();   // tile t's K/V landed
        } else {
            cp_wait<0>();
        }
        __syncthreads();

        // ---- compute tile t from buffer b ----
        const uint32_t Kb = bufb + w * 64;
        const uint32_t Vb = bufb + VOFF + w * 64;
        float* dsw = dsb + w * DSPLANE;

        float s[4][4];
#pragma unroll
        for (int n = 0; n < 4; n++) {
            float2 t0 = *(float2*)(dsw + rq * 36 + n * 8 + c2);
            float2 t1 = *(float2*)(dsw + (rq + 8) * 36 + n * 8 + c2);
            s[n][0] = t0.x; s[n][1] = t0.y; s[n][2] = t1.x; s[n][3] = t1.y;
        }
#pragma unroll
        for (int ks = 0; ks < 2; ks++)
#pragma unroll
            for (int n = 0; n < 4; n++) {
                uint32_t b0, b1;
                ldsm_x2(b0, b1, Kb + (n * 8 + (lane & 7)) * KROW
                                  + ((lane >> 3) & 1) * 16 + ks * 32);
                mma_f16(s[n], qa[ks], b0, b1);
            }

        // online softmax
        float mx0 = NINF, mx1 = NINF;
#pragma unroll
        for (int n = 0; n < 4; n++) {
            mx0 = fmaxf(mx0, fmaxf(s[n][0], s[n][1]));
            mx1 = fmaxf(mx1, fmaxf(s[n][2], s[n][3]));
        }
        mx0 = fmaxf(mx0, __shfl_xor_sync(0xffffffffu, mx0, 1));
        mx0 = fmaxf(mx0, __shfl_xor_sync(0xffffffffu, mx0, 2));
        mx1 = fmaxf(mx1, __shfl_xor_sync(0xffffffffu, mx1, 1));
        mx1 = fmaxf(mx1, __shfl_xor_sync(0xffffffffu, mx1, 2));
        float nm0 = fmaxf(m0, mx0), nm1 = fmaxf(m1, mx1);
        float cr0 = __expf(m0 - nm0), cr1 = __expf(m1 - nm1);
        m0 = nm0; m1 = nm1;
        l0 *= cr0; l1 *= cr1;
#pragma unroll
        for (int n = 0; n < 4; n++) {
            o[n][0] *= cr0; o[n][1] *= cr0; o[n][2] *= cr1; o[n][3] *= cr1;
        }

        // P = exp(S - m) packed into PV A-fragments
        uint32_t pa[2][4];
        float sm0 = 0.f, sm1 = 0.f;
#pragma unroll
        for (int n = 0; n < 4; n++) {
            float p0 = __expf(s[n][0] - m0), p1 = __expf(s[n][1] - m0);
            float p2 = __expf(s[n][2] - m1), p3 = __expf(s[n][3] - m1);
            sm0 += p0 + p1; sm1 += p2 + p3;
            int j = n >> 1;
            if ((n & 1) == 0) { pa[j][0] = pkhf(p0, p1); pa[j][1] = pkhf(p2, p3); }
            else              { pa[j][2] = pkhf(p0, p1); pa[j][3] = pkhf(p2, p3); }
        }
        l0 += sm0; l1 += sm1;

        // O += P V
#pragma unroll
        for (int j = 0; j < 2; j++)
#pragma unroll
            for (int nn = 0; nn < 4; nn++) {
                uint32_t b0, b1;
                ldsm_x2_t(b0, b1, Vb + (16 * j + (lane & 15)) * KROW + nn * 16);
                mma_f16(o[nn], pa[j], b0, b1);
            }
        __syncthreads();   // protect buffer b before next cp.async cycle targets it
    }

    // reduce row sums across quad
    l0 += __shfl_xor_sync(0xffffffffu, l0, 1);
    l0 += __shfl_xor_sync(0xffffffffu, l0, 2);
    l1 += __shfl_xor_sync(0xffffffffu, l1, 1);
    l1 += __shfl_xor_sync(0xffffffffu, l1, 2);

    // store split-K partials
    const size_t i0 = ((size_t)(sp * Qn + q0 + rq) * Hh + w) * CH;
    const size_t i1 = ((size_t)(sp * Qn + q0 + rq + 8) * Hh + w) * CH;
#pragma unroll
    for (int nn = 0; nn < 4; nn++) {
        *(float2*)(g_pacc + i0 + nn * 8 + c2) = make_float2(o[nn][0], o[nn][1]);
        *(float2*)(g_pacc + i1 + nn * 8 + c2) = make_float2(o[nn][2], o[nn][3]);
    }
    if ((lane & 3) == 0) {
        g_pm[(size_t)(sp * Qn + q0 + rq) * Hh + w] = m0;
        g_pl[(size_t)(sp * Qn + q0 + rq) * Hh + w] = l0;
        g_pm[(size_t)(sp * Qn + q0 + rq + 8) * Hh + w] = m1;
        g_pl[(size_t)(sp * Qn + q0 + rq + 8) * Hh + w] = l1;
    }
}

// ---------------- kernel 3: split-K merge + normalize + gate ----------------
__global__ __launch_bounds__(256) void merge_kernel() {
    const int tid = threadIdx.x;
    const int h  = tid & 7;
    const int ql = tid >> 3;
    const int q  = blockIdx.x * 32 + ql;
    const int idx = q * Hh + h;

    float mj[SPLITK], lj[SPLITK];
    float M = -__int_as_float(0x7f800000);
#pragma unroll
    for (int j = 0; j < SPLITK; j++) {
        mj[j] = g_pm[j * Qn * Hh + idx];
        lj[j] = g_pl[j * Qn * Hh + idx];
        M = fmaxf(M, mj[j]);
    }
    float w[SPLITK], L = 0.f;
#pragma unroll
    for (int j = 0; j < SPLITK; j++) {
        w[j] = __expf(mj[j] - M);
        L += w[j] * lj[j];
    }
    const float inv = 1.f / L;

    const float4* gate = (const float4*)(g_g + q * HD + h * CH);
    float4* outp       = (float4*)(g_o + q * HD + h * CH);
#pragma unroll
    for (int c4 = 0; c4 < 8; c4++) {
        float4 a = make_float4(0.f, 0.f, 0.f, 0.f);
#pragma unroll
        for (int j = 0; j < SPLITK; j++) {
            const float4 pj = ((const float4*)g_pacc)[(size_t)(j * Qn * Hh + idx) * 8 + c4];
            a.x += w[j] * pj.x; a.y += w[j] * pj.y;
            a.z += w[j] * pj.z; a.w += w[j] * pj.w;
        }
        float4 g = gate[c4];
        a.x *= inv * g.x; a.y *= inv * g.y; a.z *= inv * g.z; a.w *= inv * g.w;
        outp[c4] = a;
    }
}

// ---------------- kernel 4: output projection ----------------
__global__ __launch_bounds__(256) void out_kernel(const float* __restrict__ Wo,
                                                  const float* __restrict__ bo,
                                                  float* __restrict__ out) {
    gemm_tile<16>(g_o, Wo, bo, out, Cin, HD, 4);
}

// ---------------- launch ----------------
extern "C" void kernel_launch(void* const* d_in, const int* in_sizes, int n_in,
                              void* d_out, int out_size) {
    (void)in_sizes; (void)n_in; (void)out_size;
    const float* qx   = (const float*)d_in[0];
    const float* kvx  = (const float*)d_in[1];
    const float* bias = (const float*)d_in[2];
    const float* dist = (const float*)d_in[3];
    const float* Wq   = (const float*)d_in[4];
    const float* Wk   = (const float*)d_in[5];
    const float* Wv   = (const float*)d_in[6];
    const float* Wg   = (const float*)d_in[7];
    const float* bg   = (const float*)d_in[8];
    const float* Wo   = (const float*)d_in[9];
    const float* bo   = (const float*)d_in[10];
    float* out = (float*)d_out;

    cudaFuncSetAttribute(attn_kernel, cudaFuncAttributeMaxDynamicSharedMemorySize,
                         SM_BYTES);

    proj_kernel<<<dim3(Qn / 64, HD / 64, 4), 256>>>(qx, kvx, Wq, Wk, Wv, Wg, bg);
    attn_kernel<<<dim3(Qn / TQ, SPLITK), 256, SM_BYTES>>>(bias, dist);
    merge_kernel<<<dim3(Qn / 32), 256>>>();
    out_kernel<<<dim3(Qn / 16, Cin / 64), 256>>>(Wo, bo, out);
}

// round 13
// speedup vs baseline: 4.7637x; 1.1513x over previous
#include <cuda_runtime.h>
#include <cuda_fp16.h>
#include <stdint.h>

#define Qn   2048
#define Kn   2048
#define Cin  128
#define HD   256
#define Hh   8
#define CH   32

#define SPLITK 2
#define KS     (Kn / SPLITK)   // 1024 keys per block
#define KT     32              // keys per smem tile
#define NTILES (KS / KT)       // 32
#define TQ     16              // q rows per block

// attn per-buffer smem layout (bytes)
#define KROW     528
#define VOFF     16896
#define DSOFF    33792
#define DSPLANE  576
#define BUFB     52224
#define SM_BYTES (2 * BUFB)    // 104448

// proj_h smem
#define PA_PITCH 136
#define PB_PITCH 72
#define PJ_SMEM  (128 * PA_PITCH * 2 + 128 * PB_PITCH * 2)   // 53248

// out_h smem (BM=32, BN=64, kc=128, K=768)
#define OA_PITCH 136
#define OB_PITCH 72
#define OA_BYTES (32 * OA_PITCH * 2)    // 8704
#define OB_BYTES (128 * OB_PITCH * 2)   // 18432
#define OBUF     (OA_BYTES + OB_BYTES)  // 27136
#define OUT_SMEM (2 * OBUF)             // 54272

// ---------------- scratch ----------------
__device__ __align__(16) __half g_qh[Qn * HD];    // q/sqrt(32)
__device__ __align__(16) __half g_kh[Kn * HD];
__device__ __align__(16) __half g_vh[Kn * HD];
__device__ __align__(16) float  g_g[Qn * HD];     // sigmoid gate
__device__ __align__(16) float  g_pacc[SPLITK * Qn * Hh * CH];
__device__ __align__(16) float  g_pm[SPLITK * Qn * Hh];
__device__ __align__(16) float  g_pl[SPLITK * Qn * Hh];
__device__ __align__(16) __half g_x16q[Qn * Cin];
__device__ __align__(16) __half g_x16kv[Kn * Cin];
__device__ __align__(16) __half g_w16[4][Cin * HD];   // Wq,Wk,Wv,Wg fp16
__device__ __align__(16) __half g_w2[768 * Cin];      // [Wo_hi; Wo_lo; Wo_hi]
__device__ __align__(16) __half g_ohi[Qn * HD];       // gated out, fp16 hi
__device__ __align__(16) __half g_olo[Qn * HD];       // fp16 residual

// ---------------- asm helpers ----------------
__device__ __forceinline__ uint32_t smem_u32(const void* p) {
    return (uint32_t)__cvta_generic_to_shared(p);
}
__device__ __forceinline__ void cpasync16(uint32_t dst, const void* src) {
    asm volatile("cp.async.cg.shared.global [%0], [%1], 16;" :: "r"(dst), "l"(src));
}
__device__ __forceinline__ void cp_commit() {
    asm volatile("cp.async.commit_group;");
}
template <int N>
__device__ __forceinline__ void cp_wait() {
    asm volatile("cp.async.wait_group %0;" :: "n"(N));
}
__device__ __forceinline__ void ldsm_x2(uint32_t& r0, uint32_t& r1, uint32_t a) {
    asm volatile("ldmatrix.sync.aligned.m8n8.x2.shared.b16 {%0,%1},[%2];"
                 : "=r"(r0), "=r"(r1) : "r"(a));
}
__device__ __forceinline__ void ldsm_x2_t(uint32_t& r0, uint32_t& r1, uint32_t a) {
    asm volatile("ldmatrix.sync.aligned.m8n8.x2.trans.shared.b16 {%0,%1},[%2];"
                 : "=r"(r0), "=r"(r1) : "r"(a));
}
__device__ __forceinline__ void ldsm_x4(uint32_t* r, uint32_t a) {
    asm volatile("ldmatrix.sync.aligned.m8n8.x4.shared.b16 {%0,%1,%2,%3},[%4];"
                 : "=r"(r[0]), "=r"(r[1]), "=r"(r[2]), "=r"(r[3]) : "r"(a));
}
__device__ __forceinline__ void mma_f16(float* c, const uint32_t* a, uint32_t b0, uint32_t b1) {
    asm volatile("mma.sync.aligned.m16n8k16.row.col.f32.f16.f16.f32 "
                 "{%0,%1,%2,%3},{%4,%5,%6,%7},{%8,%9},{%0,%1,%2,%3};"
                 : "+f"(c[0]), "+f"(c[1]), "+f"(c[2]), "+f"(c[3])
                 : "r"(a[0]), "r"(a[1]), "r"(a[2]), "r"(a[3]), "r"(b0), "r"(b1));
}
__device__ __forceinline__ uint32_t pkhf(float lo, float hi) {
    __half2 h = __floats2half2_rn(lo, hi);
    return *reinterpret_cast<uint32_t*>(&h);
}

// ---------------- kernel 0: fp32 -> fp16 conversions (+ Wo hi/lo split) -------------
__global__ __launch_bounds__(256) void convert_kernel(const float* __restrict__ qx,
                                                      const float* __restrict__ kvx,
                                                      const float* __restrict__ Wq,
                                                      const float* __restrict__ Wk,
                                                      const float* __restrict__ Wv,
                                                      const float* __restrict__ Wg,
                                                      const float* __restrict__ Wo) {
    const int z = blockIdx.y;
    const float* src;
    __half* dst = nullptr;
    int n4;
    if (z == 0)      { src = qx;  dst = g_x16q;  n4 = Qn * Cin / 4; }
    else if (z == 1) { src = kvx; dst = g_x16kv; n4 = Kn * Cin / 4; }
    else if (z == 2) { src = Wq; dst = g_w16[0]; n4 = Cin * HD / 4; }
    else if (z == 3) { src = Wk; dst = g_w16[1]; n4 = Cin * HD / 4; }
    else if (z == 4) { src = Wv; dst = g_w16[2]; n4 = Cin * HD / 4; }
    else if (z == 5) { src = Wg; dst = g_w16[3]; n4 = Cin * HD / 4; }
    else             { src = Wo; n4 = HD * Cin / 4; }

    for (int i = blockIdx.x * blockDim.x + threadIdx.x; i < n4;
         i += gridDim.x * blockDim.x) {
        float4 v = ((const float4*)src)[i];
        __half2 h0 = __floats2half2_rn(v.x, v.y);
        __half2 h1 = __floats2half2_rn(v.z, v.w);
        if (z < 6) {
            ((__half2*)dst)[2 * i]     = h0;
            ((__half2*)dst)[2 * i + 1] = h1;
        } else {
            __half2 l0 = __floats2half2_rn(v.x - __half2float(h0.x),
                                           v.y - __half2float(h0.y));
            __half2 l1 = __floats2half2_rn(v.z - __half2float(h1.x),
                                           v.w - __half2float(h1.y));
            int e = 4 * i;
            int row = e >> 7, col = e & 127;
            __half* b0 = g_w2 + (size_t)row * Cin + col;           // hi
            *(__half2*)b0 = h0;            *(__half2*)(b0 + 2) = h1;
            __half* b1 = b0 + 256 * Cin;                            // lo
            *(__half2*)b1 = l0;            *(__half2*)(b1 + 2) = l1;
            __half* b2 = b0 + 512 * Cin;                            // hi again
            *(__half2*)b2 = h0;            *(__half2*)(b2 + 2) = h1;
        }
    }
}

// ---------------- kernel 1: projections via HMMA --------------------------------------
// z: 0 q (scale 1/sqrt32 -> g_qh), 1 k -> g_kh, 2 v -> g_vh, 3 gate -> g_g (sigmoid+bg)
__global__ __launch_bounds__(256) void proj_h(const float* __restrict__ bg) {
    extern __shared__ char sm[];
    __half* As = (__half*)sm;                          // [128][PA_PITCH]
    __half* Bs = (__half*)(sm + 128 * PA_PITCH * 2);   // [128][PB_PITCH]
    const int tid = threadIdx.x, w = tid >> 5, lane = tid & 31;
    const int bm = blockIdx.x, bn = blockIdx.y, z = blockIdx.z;
    const __half* A16 = (z == 0 || z == 3) ? g_x16q : g_x16kv;
    const __half* B16 = g_w16[z];

#pragma unroll
    for (int r = 0; r < 8; r++) {
        int idx = tid + 256 * r;
        int row = idx >> 4, c = idx & 15;
        *(float4*)(As + row * PA_PITCH + c * 8) =
            *(const float4*)(A16 + (size_t)(bm * 128 + row) * Cin + c * 8);
    }
#pragma unroll
    for (int r = 0; r < 4; r++) {
        int idx = tid + 256 * r;
        int row = idx >> 3, c = idx & 7;
        *(float4*)(Bs + row * PB_PITCH + c * 8) =
            *(const float4*)(B16 + (size_t)row * HD + bn * 64 + c * 8);
    }
    __syncthreads();

    const uint32_t Ab = smem_u32(As) +
        (((16 * w + ((lane >> 3) & 1) * 8 + (lane & 7)) * PA_PITCH) + ((lane >> 4) & 1) * 8) * 2;
    const uint32_t Bb = smem_u32(Bs) + ((lane & 15) * PB_PITCH) * 2;

    float c[8][4];
#pragma unroll
    for (int n = 0; n < 8; n++)
#pragma unroll
        for (int j = 0; j < 4; j++) c[n][j] = 0.f;

#pragma unroll
    for (int ks = 0; ks < 8; ks++) {
        uint32_t a[4];
        ldsm_x4(a, Ab + ks * 32);
#pragma unroll
        for (int nf = 0; nf < 8; nf++) {
            uint32_t b0, b1;
            ldsm_x2_t(b0, b1, Bb + (ks * 16 * PB_PITCH + nf * 8) * 2);
            mma_f16(c[nf], a, b0, b1);
        }
    }

    const int rq = lane >> 2, c2 = (lane & 3) * 2;
    const int row = bm * 128 + 16 * w + rq;
    if (z == 3) {
#pragma unroll
        for (int nf = 0; nf < 8; nf++) {
            int col = bn * 64 + nf * 8 + c2;
            float b0 = bg[col], b1 = bg[col + 1];
            *(float2*)(g_g + (size_t)row * HD + col) = make_float2(
                1.f / (1.f + __expf(-(c[nf][0] + b0))),
                1.f / (1.f + __expf(-(c[nf][1] + b1))));
            *(float2*)(g_g + (size_t)(row + 8) * HD + col) = make_float2(
                1.f / (1.f + __expf(-(c[nf][2] + b0))),
                1.f / (1.f + __expf(-(c[nf][3] + b1))));
        }
    } else {
        __half* dst = (z == 0) ? g_qh : (z == 1) ? g_kh : g_vh;
        const float sc = (z == 0) ? 0.17677669529663689f : 1.f;
#pragma unroll
        for (int nf = 0; nf < 8; nf++) {
            int col = bn * 64 + nf * 8 + c2;
            *(__half2*)(dst + (size_t)row * HD + col) =
                __floats2half2_rn(c[nf][0] * sc, c[nf][1] * sc);
            *(__half2*)(dst + (size_t)(row + 8) * HD + col) =
                __floats2half2_rn(c[nf][2] * sc, c[nf][3] * sc);
        }
    }
}

// ---------------- kernel 2: flash attention (unchanged from R10) ----------------------
__global__ __launch_bounds__(256, 2) void attn_kernel(const float* __restrict__ bias,
                                                      const float* __restrict__ dist) {
    extern __shared__ char smem[];
    const int tid  = threadIdx.x;
    const int w    = tid >> 5;
    const int lane = tid & 31;
    const int q0   = blockIdx.x * TQ;
    const int sp   = blockIdx.y;
    const int kb0  = sp * KS;
    const int rq   = lane >> 2;
    const int c2   = (lane & 3) * 2;

    const uint32_t sb = smem_u32(smem);

    uint32_t qa[2][4];
    {
        const __half* qp = g_qh + (size_t)(q0 + rq) * HD + w * CH + c2;
#pragma unroll
        for (int s = 0; s < 2; s++) {
            qa[s][0] = *(const uint32_t*)(qp + s * 16);
            qa[s][1] = *(const uint32_t*)(qp + 8 * HD + s * 16);
            qa[s][2] = *(const uint32_t*)(qp + s * 16 + 8);
            qa[s][3] = *(const uint32_t*)(qp + 8 * HD + s * 16 + 8);
        }
    }

    float o[4][4];
#pragma unroll
    for (int n = 0; n < 4; n++)
#pragma unroll
        for (int j = 0; j < 4; j++) o[n][j] = 0.f;
    const float NINF = -__int_as_float(0x7f800000);
    float m0 = NINF, m1 = NINF, l0 = 0.f, l1 = 0.f;

    float4 dreg[4];
    float  breg[4];

    {
        const int kb = kb0;
#pragma unroll
        for (int r = 0; r < 4; r++) {
            int idx = tid + 256 * r;
            int row = idx >> 5, c = idx & 31;
            cpasync16(sb + row * KROW + c * 16, g_kh + (size_t)(kb + row) * HD + c * 8);
            cpasync16(sb + VOFF + row * KROW + c * 16, g_vh + (size_t)(kb + row) * HD + c * 8);
        }
        cp_commit();
#pragma unroll
        for (int r = 0; r < 4; r++) {
            int idx = tid + 256 * r;
            int h4 = (idx & 1) * 4, k = (idx >> 1) & 31, q = idx >> 6;
            dreg[r] = *(const float4*)(dist + ((size_t)(q0 + q) * Kn + kb + k) * Hh + h4);
            breg[r] = __ldg(bias + (size_t)(q0 + q) * Kn + kb + k);
        }
    }

    for (int t = 0; t < NTILES; t++) {
        const int b = t & 1;
        const uint32_t bufb = sb + b * BUFB;
        float* dsb = (float*)(smem + b * BUFB + DSOFF);

#pragma unroll
        for (int r = 0; r < 4; r++) {
            int idx = tid + 256 * r;
            int h4 = (idx & 1) * 4, k = (idx >> 1) & 31, q = idx >> 6;
            float* dp = dsb + h4 * DSPLANE + q * 36 + k;
            float bb = breg[r];
            dp[0]           = dreg[r].x + bb;
            dp[DSPLANE]     = dreg[r].y + bb;
            dp[2 * DSPLANE] = dreg[r].z + bb;
            dp[3 * DSPLANE] = dreg[r].w + bb;
        }

        if (t + 1 < NTILES) {
            const int kb = kb0 + (t + 1) * KT;
            const uint32_t nb = sb + (b ^ 1) * BUFB;
#pragma unroll
            for (int r = 0; r < 4; r++) {
                int idx = tid + 256 * r;
                int row = idx >> 5, c = idx & 31;
                cpasync16(nb + row * KROW + c * 16, g_kh + (size_t)(kb + row) * HD + c * 8);
                cpasync16(nb + VOFF + row * KROW + c * 16, g_vh + (size_t)(kb + row) * HD + c * 8);
            }
            cp_commit();
#pragma unroll
            for (int r = 0; r < 4; r++) {
                int idx = tid + 256 * r;
                int h4 = (idx & 1) * 4, k = (idx >> 1) & 31, q = idx >> 6;
                dreg[r] = *(const float4*)(dist + ((size_t)(q0 + q) * Kn + kb + k) * Hh + h4);
                breg[r] = __ldg(bias + (size_t)(q0 + q) * Kn + kb + k);
            }
            cp_wait<1>();
        } else {
            cp_wait<0>();
        }
        __syncthreads();

        const uint32_t Kb = bufb + w * 64;
        const uint32_t Vb = bufb + VOFF + w * 64;
        float* dsw = dsb + w * DSPLANE;

        float s[4][4];
#pragma unroll
        for (int n = 0; n < 4; n++) {
            float2 t0 = *(float2*)(dsw + rq * 36 + n * 8 + c2);
            float2 t1 = *(float2*)(dsw + (rq + 8) * 36 + n * 8 + c2);
            s[n][0] = t0.x; s[n][1] = t0.y; s[n][2] = t1.x; s[n][3] = t1.y;
        }
#pragma unroll
        for (int ks = 0; ks < 2; ks++)
#pragma unroll
            for (int n = 0; n < 4; n++) {
                uint32_t b0, b1;
                ldsm_x2(b0, b1, Kb + (n * 8 + (lane & 7)) * KROW
                                  + ((lane >> 3) & 1) * 16 + ks * 32);
                mma_f16(s[n], qa[ks], b0, b1);
            }

        float mx0 = NINF, mx1 = NINF;
#pragma unroll
        for (int n = 0; n < 4; n++) {
            mx0 = fmaxf(mx0, fmaxf(s[n][0], s[n][1]));
            mx1 = fmaxf(mx1, fmaxf(s[n][2], s[n][3]));
        }
        mx0 = fmaxf(mx0, __shfl_xor_sync(0xffffffffu, mx0, 1));
        mx0 = fmaxf(mx0, __shfl_xor_sync(0xffffffffu, mx0, 2));
        mx1 = fmaxf(mx1, __shfl_xor_sync(0xffffffffu, mx1, 1));
        mx1 = fmaxf(mx1, __shfl_xor_sync(0xffffffffu, mx1, 2));
        float nm0 = fmaxf(m0, mx0), nm1 = fmaxf(m1, mx1);
        float cr0 = __expf(m0 - nm0), cr1 = __expf(m1 - nm1);
        m0 = nm0; m1 = nm1;
        l0 *= cr0; l1 *= cr1;
#pragma unroll
        for (int n = 0; n < 4; n++) {
            o[n][0] *= cr0; o[n][1] *= cr0; o[n][2] *= cr1; o[n][3] *= cr1;
        }

        uint32_t pa[2][4];
        float sm0 = 0.f, sm1 = 0.f;
#pragma unroll
        for (int n = 0; n < 4; n++) {
            float p0 = __expf(s[n][0] - m0), p1 = __expf(s[n][1] - m0);
            float p2 = __expf(s[n][2] - m1), p3 = __expf(s[n][3] - m1);
            sm0 += p0 + p1; sm1 += p2 + p3;
            int j = n >> 1;
            if ((n & 1) == 0) { pa[j][0] = pkhf(p0, p1); pa[j][1] = pkhf(p2, p3); }
            else              { pa[j][2] = pkhf(p0, p1); pa[j][3] = pkhf(p2, p3); }
        }
        l0 += sm0; l1 += sm1;

#pragma unroll
        for (int j = 0; j < 2; j++)
#pragma unroll
            for (int nn = 0; nn < 4; nn++) {
                uint32_t b0, b1;
                ldsm_x2_t(b0, b1, Vb + (16 * j + (lane & 15)) * KROW + nn * 16);
                mma_f16(o[nn], pa[j], b0, b1);
            }
        __syncthreads();
    }

    l0 += __shfl_xor_sync(0xffffffffu, l0, 1);
    l0 += __shfl_xor_sync(0xffffffffu, l0, 2);
    l1 += __shfl_xor_sync(0xffffffffu, l1, 1);
    l1 += __shfl_xor_sync(0xffffffffu, l1, 2);

    const size_t i0 = ((size_t)(sp * Qn + q0 + rq) * Hh + w) * CH;
    const size_t i1 = ((size_t)(sp * Qn + q0 + rq + 8) * Hh + w) * CH;
#pragma unroll
    for (int nn = 0; nn < 4; nn++) {
        *(float2*)(g_pacc + i0 + nn * 8 + c2) = make_float2(o[nn][0], o[nn][1]);
        *(float2*)(g_pacc + i1 + nn * 8 + c2) = make_float2(o[nn][2], o[nn][3]);
    }
    if ((lane & 3) == 0) {
        g_pm[(size_t)(sp * Qn + q0 + rq) * Hh + w] = m0;
        g_pl[(size_t)(sp * Qn + q0 + rq) * Hh + w] = l0;
        g_pm[(size_t)(sp * Qn + q0 + rq + 8) * Hh + w] = m1;
        g_pl[(size_t)(sp * Qn + q0 + rq + 8) * Hh + w] = l1;
    }
}

// ---------------- kernel 3: split-K merge + normalize + gate -> fp16 hi/lo ------------
__global__ __launch_bounds__(256) void merge_kernel() {
    const int tid = threadIdx.x;
    const int h  = tid & 7;
    const int ql = tid >> 3;
    const int q  = blockIdx.x * 32 + ql;
    const int idx = q * Hh + h;

    float mj[SPLITK], lj[SPLITK];
    float M = -__int_as_float(0x7f800000);
#pragma unroll
    for (int j = 0; j < SPLITK; j++) {
        mj[j] = g_pm[j * Qn * Hh + idx];
        lj[j] = g_pl[j * Qn * Hh + idx];
        M = fmaxf(M, mj[j]);
    }
    float w[SPLITK], L = 0.f;
#pragma unroll
    for (int j = 0; j < SPLITK; j++) {
        w[j] = __expf(mj[j] - M);
        L += w[j] * lj[j];
    }
    const float inv = 1.f / L;

    const float4* gate = (const float4*)(g_g + q * HD + h * CH);
    __half* ph = g_ohi + (size_t)q * HD + h * CH;
    __half* pl = g_olo + (size_t)q * HD + h * CH;
#pragma unroll
    for (int c4 = 0; c4 < 8; c4++) {
        float4 a = make_float4(0.f, 0.f, 0.f, 0.f);
#pragma unroll
        for (int j = 0; j < SPLITK; j++) {
            const float4 pj = ((const float4*)g_pacc)[(size_t)(j * Qn * Hh + idx) * 8 + c4];
            a.x += w[j] * pj.x; a.y += w[j] * pj.y;
            a.z += w[j] * pj.z; a.w += w[j] * pj.w;
        }
        float4 g = gate[c4];
        a.x *= inv * g.x; a.y *= inv * g.y; a.z *= inv * g.z; a.w *= inv * g.w;
        __half2 h0 = __floats2half2_rn(a.x, a.y);
        __half2 h1 = __floats2half2_rn(a.z, a.w);
        __half2 l0 = __floats2half2_rn(a.x - __half2float(h0.x),
                                       a.y - __half2float(h0.y));
        __half2 l1 = __floats2half2_rn(a.z - __half2float(h1.x),
                                       a.w - __half2float(h1.y));
        *(__half2*)(ph + c4 * 4)     = h0;
        *(__half2*)(ph + c4 * 4 + 2) = h1;
        *(__half2*)(pl + c4 * 4)     = l0;
        *(__half2*)(pl + c4 * 4 + 2) = l1;
    }
}

// ---------------- kernel 4: output projection via HMMA (hi/lo compensated) ------------
// C[2048x128] = [o_hi | o_hi | o_lo][2048x768] @ [Wo_hi; Wo_lo; Wo_hi][768x128] + bo
__global__ __launch_bounds__(256) void out_h(const float* __restrict__ bo,
                                             float* __restrict__ out) {
    extern __shared__ char sm[];
    const int tid = threadIdx.x, w = tid >> 5, lane = tid & 31;
    const int bm = blockIdx.x, bn = blockIdx.y;
    const int wm = w & 1, wn = w >> 1;
    const uint32_t sb = smem_u32(sm);

    auto stage = [&](int t, int buf) {
        const __half* arr = (t < 4) ? g_ohi : g_olo;
        const int colbase = (t & 1) * 128;
        const uint32_t ab = sb + buf * OBUF;
        const uint32_t bb = ab + OA_BYTES;
#pragma unroll
        for (int r = 0; r < 2; r++) {
            int idx = tid + 256 * r;
            int row = idx >> 4, c = idx & 15;
            cpasync16(ab + (row * OA_PITCH + c * 8) * 2,
                      arr + (size_t)(bm * 32 + row) * HD + colbase + c * 8);
        }
#pragma unroll
        for (int r = 0; r < 4; r++) {
            int idx = tid + 256 * r;
            int row = idx >> 3, c = idx & 7;
            cpasync16(bb + (row * OB_PITCH + c * 8) * 2,
                      g_w2 + (size_t)(t * 128 + row) * Cin + bn * 64 + c * 8);
        }
        cp_commit();
    };

    float c[2][4];
#pragma unroll
    for (int n = 0; n < 2; n++)
#pragma unroll
        for (int j = 0; j < 4; j++) c[n][j] = 0.f;

    stage(0, 0);
    for (int t = 0; t < 6; t++) {
        const int b = t & 1;
        if (t + 1 < 6) { stage(t + 1, b ^ 1); cp_wait<1>(); }
        else           { cp_wait<0>(); }
        __syncthreads();

        const uint32_t ab = sb + b * OBUF;
        const uint32_t bb = ab + OA_BYTES;
        const uint32_t Ab = ab +
            (((16 * wm + ((lane >> 3) & 1) * 8 + (lane & 7)) * OA_PITCH) + ((lane >> 4) & 1) * 8) * 2;
        const uint32_t Bb = bb + ((lane & 15) * OB_PITCH + wn * 16) * 2;

#pragma unroll
        for (int ks = 0; ks < 8; ks++) {
            uint32_t a[4];
            ldsm_x4(a, Ab + ks * 32);
#pragma unroll
            for (int nf = 0; nf < 2; nf++) {
                uint32_t b0, b1;
                ldsm_x2_t(b0, b1, Bb + (ks * 16 * OB_PITCH + nf * 8) * 2);
                mma_f16(c[nf], a, b0, b1);
            }
        }
        __syncthreads();
    }

    const int rq = lane >> 2, c2 = (lane & 3) * 2;
    const int row = bm * 32 + 16 * wm + rq;
#pragma unroll
    for (int nf = 0; nf < 2; nf++) {
        int col = bn * 64 + wn * 16 + nf * 8 + c2;
        float b0 = bo[col], b1 = bo[col + 1];
        *(float2*)(out + (size_t)row * Cin + col) =
            make_float2(c[nf][0] + b0, c[nf][1] + b1);
        *(float2*)(out + (size_t)(row + 8) * Cin + col) =
            make_float2(c[nf][2] + b0, c[nf][3] + b1);
    }
}

// ---------------- launch --------------------------------------------------------------
extern "C" void kernel_launch(void* const* d_in, const int* in_sizes, int n_in,
                              void* d_out, int out_size) {
    (void)in_sizes; (void)n_in; (void)out_size;
    const float* qx   = (const float*)d_in[0];
    const float* kvx  = (const float*)d_in[1];
    const float* bias = (const float*)d_in[2];
    const float* dist = (const float*)d_in[3];
    const float* Wq   = (const float*)d_in[4];
    const float* Wk   = (const float*)d_in[5];
    const float* Wv   = (const float*)d_in[6];
    const float* Wg   = (const float*)d_in[7];
    const float* bg   = (const float*)d_in[8];
    const float* Wo   = (const float*)d_in[9];
    const float* bo   = (const float*)d_in[10];
    float* out = (float*)d_out;

    cudaFuncSetAttribute(attn_kernel, cudaFuncAttributeMaxDynamicSharedMemorySize, SM_BYTES);
    cudaFuncSetAttribute(proj_h,      cudaFuncAttributeMaxDynamicSharedMemorySize, PJ_SMEM);
    cudaFuncSetAttribute(out_h,       cudaFuncAttributeMaxDynamicSharedMemorySize, OUT_SMEM);

    convert_kernel<<<dim3(32, 7), 256>>>(qx, kvx, Wq, Wk, Wv, Wg, Wo);
    proj_h<<<dim3(Qn / 128, HD / 64, 4), 256, PJ_SMEM>>>(bg);
    attn_kernel<<<dim3(Qn / TQ, SPLITK), 256, SM_BYTES>>>(bias, dist);
    merge_kernel<<<dim3(Qn / 32), 256>>>();
    out_h<<<dim3(Qn / 32, Cin / 64), 256, OUT_SMEM>>>(bo, out);
}

// round 14
// speedup vs baseline: 5.3396x; 1.1209x over previous
#include <cuda_runtime.h>
#include <cuda_fp16.h>
#include <stdint.h>

#define Qn   2048
#define Kn   2048
#define Cin  128
#define HD   256
#define Hh   8
#define CH   32

#define SPLITK 2
#define KS     (Kn / SPLITK)   // 1024 keys per block
#define KT     32              // keys per smem tile
#define NTILES (KS / KT)       // 32
#define TQ     32              // q rows per block (2 halves x 16)

// attn per-buffer smem layout (bytes)
#define KROW     528
#define VOFF     16896                  // 32*528
#define DSOFF    33792                  // VOFF + 32*528
#define DSPLANE  1152                   // floats per head plane (32q*36)
#define BUFB     70656                  // DSOFF + 8*1152*4
#define SM_BYTES (2 * BUFB)             // 141312

// proj_h smem
#define PA_PITCH 136
#define PB_PITCH 72
#define PJ_SMEM  (128 * PA_PITCH * 2 + 128 * PB_PITCH * 2)   // 53248

// out_h smem (BM=32, BN=64, kc=128, K=768)
#define OA_PITCH 136
#define OB_PITCH 72
#define OA_BYTES (32 * OA_PITCH * 2)    // 8704
#define OB_BYTES (128 * OB_PITCH * 2)   // 18432
#define OBUF     (OA_BYTES + OB_BYTES)  // 27136
#define OUT_SMEM (2 * OBUF)             // 54272

// ---------------- scratch ----------------
__device__ __align__(16) __half g_qh[Qn * HD];    // q/sqrt(32)
__device__ __align__(16) __half g_kh[Kn * HD];
__device__ __align__(16) __half g_vh[Kn * HD];
__device__ __align__(16) float  g_g[Qn * HD];     // sigmoid gate
__device__ __align__(16) float  g_pacc[SPLITK * Qn * Hh * CH];
__device__ __align__(16) float  g_pm[SPLITK * Qn * Hh];
__device__ __align__(16) float  g_pl[SPLITK * Qn * Hh];
__device__ __align__(16) __half g_x16q[Qn * Cin];
__device__ __align__(16) __half g_x16kv[Kn * Cin];
__device__ __align__(16) __half g_w16[4][Cin * HD];   // Wq,Wk,Wv,Wg fp16
__device__ __align__(16) __half g_w2[768 * Cin];      // [Wo_hi; Wo_lo; Wo_hi]
__device__ __align__(16) __half g_ohi[Qn * HD];       // gated out, fp16 hi
__device__ __align__(16) __half g_olo[Qn * HD];       // fp16 residual

// ---------------- asm helpers ----------------
__device__ __forceinline__ uint32_t smem_u32(const void* p) {
    return (uint32_t)__cvta_generic_to_shared(p);
}
__device__ __forceinline__ void cpasync16(uint32_t dst, const void* src) {
    asm volatile("cp.async.cg.shared.global [%0], [%1], 16;" :: "r"(dst), "l"(src));
}
__device__ __forceinline__ void cp_commit() {
    asm volatile("cp.async.commit_group;");
}
template <int N>
__device__ __forceinline__ void cp_wait() {
    asm volatile("cp.async.wait_group %0;" :: "n"(N));
}
__device__ __forceinline__ void ldsm_x2(uint32_t& r0, uint32_t& r1, uint32_t a) {
    asm volatile("ldmatrix.sync.aligned.m8n8.x2.shared.b16 {%0,%1},[%2];"
                 : "=r"(r0), "=r"(r1) : "r"(a));
}
__device__ __forceinline__ void ldsm_x2_t(uint32_t& r0, uint32_t& r1, uint32_t a) {
    asm volatile("ldmatrix.sync.aligned.m8n8.x2.trans.shared.b16 {%0,%1},[%2];"
                 : "=r"(r0), "=r"(r1) : "r"(a));
}
__device__ __forceinline__ void ldsm_x4(uint32_t* r, uint32_t a) {
    asm volatile("ldmatrix.sync.aligned.m8n8.x4.shared.b16 {%0,%1,%2,%3},[%4];"
                 : "=r"(r[0]), "=r"(r[1]), "=r"(r[2]), "=r"(r[3]) : "r"(a));
}
__device__ __forceinline__ void mma_f16(float* c, const uint32_t* a, uint32_t b0, uint32_t b1) {
    asm volatile("mma.sync.aligned.m16n8k16.row.col.f32.f16.f16.f32 "
                 "{%0,%1,%2,%3},{%4,%5,%6,%7},{%8,%9},{%0,%1,%2,%3};"
                 : "+f"(c[0]), "+f"(c[1]), "+f"(c[2]), "+f"(c[3])
                 : "r"(a[0]), "r"(a[1]), "r"(a[2]), "r"(a[3]), "r"(b0), "r"(b1));
}
__device__ __forceinline__ uint32_t pkhf(float lo, float hi) {
    __half2 h = __floats2half2_rn(lo, hi);
    return *reinterpret_cast<uint32_t*>(&h);
}

// ---------------- kernel 0: fp32 -> fp16 conversions (+ Wo hi/lo split) -------------
__global__ __launch_bounds__(256) void convert_kernel(const float* __restrict__ qx,
                                                      const float* __restrict__ kvx,
                                                      const float* __restrict__ Wq,
                                                      const float* __restrict__ Wk,
                                                      const float* __restrict__ Wv,
                                                      const float* __restrict__ Wg,
                                                      const float* __restrict__ Wo) {
    const int z = blockIdx.y;
    const float* src;
    __half* dst = nullptr;
    int n4;
    if (z == 0)      { src = qx;  dst = g_x16q;  n4 = Qn * Cin / 4; }
    else if (z == 1) { src = kvx; dst = g_x16kv; n4 = Kn * Cin / 4; }
    else if (z == 2) { src = Wq; dst = g_w16[0]; n4 = Cin * HD / 4; }
    else if (z == 3) { src = Wk; dst = g_w16[1]; n4 = Cin * HD / 4; }
    else if (z == 4) { src = Wv; dst = g_w16[2]; n4 = Cin * HD / 4; }
    else if (z == 5) { src = Wg; dst = g_w16[3]; n4 = Cin * HD / 4; }
    else             { src = Wo; n4 = HD * Cin / 4; }

    for (int i = blockIdx.x * blockDim.x + threadIdx.x; i < n4;
         i += gridDim.x * blockDim.x) {
        float4 v = ((const float4*)src)[i];
        __half2 h0 = __floats2half2_rn(v.x, v.y);
        __half2 h1 = __floats2half2_rn(v.z, v.w);
        if (z < 6) {
            ((__half2*)dst)[2 * i]     = h0;
            ((__half2*)dst)[2 * i + 1] = h1;
        } else {
            __half2 l0 = __floats2half2_rn(v.x - __half2float(h0.x),
                                           v.y - __half2float(h0.y));
            __half2 l1 = __floats2half2_rn(v.z - __half2float(h1.x),
                                           v.w - __half2float(h1.y));
            int e = 4 * i;
            int row = e >> 7, col = e & 127;
            __half* b0 = g_w2 + (size_t)row * Cin + col;           // hi
            *(__half2*)b0 = h0;            *(__half2*)(b0 + 2) = h1;
            __half* b1 = b0 + 256 * Cin;                            // lo
            *(__half2*)b1 = l0;            *(__half2*)(b1 + 2) = l1;
            __half* b2 = b0 + 512 * Cin;                            // hi again
            *(__half2*)b2 = h0;            *(__half2*)(b2 + 2) = h1;
        }
    }
}

// ---------------- kernel 1: projections via HMMA --------------------------------------
__global__ __launch_bounds__(256) void proj_h(const float* __restrict__ bg) {
    extern __shared__ char sm[];
    __half* As = (__half*)sm;
    __half* Bs = (__half*)(sm + 128 * PA_PITCH * 2);
    const int tid = threadIdx.x, w = tid >> 5, lane = tid & 31;
    const int bm = blockIdx.x, bn = blockIdx.y, z = blockIdx.z;
    const __half* A16 = (z == 0 || z == 3) ? g_x16q : g_x16kv;
    const __half* B16 = g_w16[z];

#pragma unroll
    for (int r = 0; r < 8; r++) {
        int idx = tid + 256 * r;
        int row = idx >> 4, c = idx & 15;
        *(float4*)(As + row * PA_PITCH + c * 8) =
            *(const float4*)(A16 + (size_t)(bm * 128 + row) * Cin + c * 8);
    }
#pragma unroll
    for (int r = 0; r < 4; r++) {
        int idx = tid + 256 * r;
        int row = idx >> 3, c = idx & 7;
        *(float4*)(Bs + row * PB_PITCH + c * 8) =
            *(const float4*)(B16 + (size_t)row * HD + bn * 64 + c * 8);
    }
    __syncthreads();

    const uint32_t Ab = smem_u32(As) +
        (((16 * w + ((lane >> 3) & 1) * 8 + (lane & 7)) * PA_PITCH) + ((lane >> 4) & 1) * 8) * 2;
    const uint32_t Bb = smem_u32(Bs) + ((lane & 15) * PB_PITCH) * 2;

    float c[8][4];
#pragma unroll
    for (int n = 0; n < 8; n++)
#pragma unroll
        for (int j = 0; j < 4; j++) c[n][j] = 0.f;

#pragma unroll
    for (int ks = 0; ks < 8; ks++) {
        uint32_t a[4];
        ldsm_x4(a, Ab + ks * 32);
#pragma unroll
        for (int nf = 0; nf < 8; nf++) {
            uint32_t b0, b1;
            ldsm_x2_t(b0, b1, Bb + (ks * 16 * PB_PITCH + nf * 8) * 2);
            mma_f16(c[nf], a, b0, b1);
        }
    }

    const int rq = lane >> 2, c2 = (lane & 3) * 2;
    const int row = bm * 128 + 16 * w + rq;
    if (z == 3) {
#pragma unroll
        for (int nf = 0; nf < 8; nf++) {
            int col = bn * 64 + nf * 8 + c2;
            float b0 = bg[col], b1 = bg[col + 1];
            *(float2*)(g_g + (size_t)row * HD + col) = make_float2(
                1.f / (1.f + __expf(-(c[nf][0] + b0))),
                1.f / (1.f + __expf(-(c[nf][1] + b1))));
            *(float2*)(g_g + (size_t)(row + 8) * HD + col) = make_float2(
                1.f / (1.f + __expf(-(c[nf][2] + b0))),
                1.f / (1.f + __expf(-(c[nf][3] + b1))));
        }
    } else {
        __half* dst = (z == 0) ? g_qh : (z == 1) ? g_kh : g_vh;
        const float sc = (z == 0) ? 0.17677669529663689f : 1.f;
#pragma unroll
        for (int nf = 0; nf < 8; nf++) {
            int col = bn * 64 + nf * 8 + c2;
            *(__half2*)(dst + (size_t)row * HD + col) =
                __floats2half2_rn(c[nf][0] * sc, c[nf][1] * sc);
            *(__half2*)(dst + (size_t)(row + 8) * HD + col) =
                __floats2half2_rn(c[nf][2] * sc, c[nf][3] * sc);
        }
    }
}

// ---------------- kernel 2: flash attention (HMMA fp16, 512 thr, TQ=32) ---------------
// warp = (q-half, head): wid = qh*8 + w.  Per-warp math identical to the 256-thr version.
__global__ __launch_bounds__(512, 1) void attn_kernel(const float* __restrict__ bias,
                                                      const float* __restrict__ dist) {
    extern __shared__ char smem[];
    const int tid  = threadIdx.x;
    const int wid  = tid >> 5;
    const int w    = wid & 7;        // head
    const int qh   = wid >> 3;       // q-half (0/1)
    const int lane = tid & 31;
    const int q0   = blockIdx.x * TQ;
    const int sp   = blockIdx.y;
    const int kb0  = sp * KS;
    const int rq   = lane >> 2;
    const int c2   = (lane & 3) * 2;

    const uint32_t sb = smem_u32(smem);

    // Q A-fragments (2 k-steps over CH=32), rows q0 + qh*16 + {rq, rq+8}
    uint32_t qa[2][4];
    {
        const __half* qp = g_qh + (size_t)(q0 + qh * 16 + rq) * HD + w * CH + c2;
#pragma unroll
        for (int s = 0; s < 2; s++) {
            qa[s][0] = *(const uint32_t*)(qp + s * 16);
            qa[s][1] = *(const uint32_t*)(qp + 8 * HD + s * 16);
            qa[s][2] = *(const uint32_t*)(qp + s * 16 + 8);
            qa[s][3] = *(const uint32_t*)(qp + 8 * HD + s * 16 + 8);
        }
    }

    float o[4][4];
#pragma unroll
    for (int n = 0; n < 4; n++)
#pragma unroll
        for (int j = 0; j < 4; j++) o[n][j] = 0.f;
    const float NINF = -__int_as_float(0x7f800000);
    float m0 = NINF, m1 = NINF, l0 = 0.f, l1 = 0.f;

    float4 dreg[4];
    float  breg[4];

    // ---- prologue: start tile 0 ----
    {
        const int kb = kb0;
#pragma unroll
        for (int r = 0; r < 2; r++) {
            int idx = tid + 512 * r;
            int row = idx >> 5, c = idx & 31;
            cpasync16(sb + row * KROW + c * 16, g_kh + (size_t)(kb + row) * HD + c * 8);
            cpasync16(sb + VOFF + row * KROW + c * 16, g_vh + (size_t)(kb + row) * HD + c * 8);
        }
        cp_commit();
#pragma unroll
        for (int r = 0; r < 4; r++) {
            int idx = tid + 512 * r;
            int h4 = (idx & 1) * 4, k = (idx >> 1) & 31, q = idx >> 6;   // q 0..31
            dreg[r] = *(const float4*)(dist + ((size_t)(q0 + q) * Kn + kb + k) * Hh + h4);
            breg[r] = __ldg(bias + (size_t)(q0 + q) * Kn + kb + k);
        }
    }

    for (int t = 0; t < NTILES; t++) {
        const int b = t & 1;
        const uint32_t bufb = sb + b * BUFB;
        float* dsb = (float*)(smem + b * BUFB + DSOFF);

        // store dist(t)+bias into ds[b]
#pragma unroll
        for (int r = 0; r < 4; r++) {
            int idx = tid + 512 * r;
            int h4 = (idx & 1) * 4, k = (idx >> 1) & 31, q = idx >> 6;
            float* dp = dsb + h4 * DSPLANE + q * 36 + k;
            float bb = breg[r];
            dp[0]           = dreg[r].x + bb;
            dp[DSPLANE]     = dreg[r].y + bb;
            dp[2 * DSPLANE] = dreg[r].z + bb;
            dp[3 * DSPLANE] = dreg[r].w + bb;
        }

        if (t + 1 < NTILES) {
            const int kb = kb0 + (t + 1) * KT;
            const uint32_t nb = sb + (b ^ 1) * BUFB;
#pragma unroll
            for (int r = 0; r < 2; r++) {
                int idx = tid + 512 * r;
                int row = idx >> 5, c = idx & 31;
                cpasync16(nb + row * KROW + c * 16, g_kh + (size_t)(kb + row) * HD + c * 8);
                cpasync16(nb + VOFF + row * KROW + c * 16, g_vh + (size_t)(kb + row) * HD + c * 8);
            }
            cp_commit();
#pragma unroll
            for (int r = 0; r < 4; r++) {
                int idx = tid + 512 * r;
                int h4 = (idx & 1) * 4, k = (idx >> 1) & 31, q = idx >> 6;
                dreg[r] = *(const float4*)(dist + ((size_t)(q0 + q) * Kn + kb + k) * Hh + h4);
                breg[r] = __ldg(bias + (size_t)(q0 + q) * Kn + kb + k);
            }
            cp_wait<1>();
        } else {
            cp_wait<0>();
        }
        __syncthreads();

        // ---- compute tile t from buffer b ----
        const uint32_t Kb = bufb + w * 64;
        const uint32_t Vb = bufb + VOFF + w * 64;
        float* dsw = dsb + w * DSPLANE + (qh * 16) * 36;

        float s[4][4];
#pragma unroll
        for (int n = 0; n < 4; n++) {
            float2 t0 = *(float2*)(dsw + rq * 36 + n * 8 + c2);
            float2 t1 = *(float2*)(dsw + (rq + 8) * 36 + n * 8 + c2);
            s[n][0] = t0.x; s[n][1] = t0.y; s[n][2] = t1.x; s[n][3] = t1.y;
        }
#pragma unroll
        for (int ks = 0; ks < 2; ks++)
#pragma unroll
            for (int n = 0; n < 4; n++) {
                uint32_t b0, b1;
                ldsm_x2(b0, b1, Kb + (n * 8 + (lane & 7)) * KROW
                                  + ((lane >> 3) & 1) * 16 + ks * 32);
                mma_f16(s[n], qa[ks], b0, b1);
            }

        // online softmax
        float mx0 = NINF, mx1 = NINF;
#pragma unroll
        for (int n = 0; n < 4; n++) {
            mx0 = fmaxf(mx0, fmaxf(s[n][0], s[n][1]));
            mx1 = fmaxf(mx1, fmaxf(s[n][2], s[n][3]));
        }
        mx0 = fmaxf(mx0, __shfl_xor_sync(0xffffffffu, mx0, 1));
        mx0 = fmaxf(mx0, __shfl_xor_sync(0xffffffffu, mx0, 2));
        mx1 = fmaxf(mx1, __shfl_xor_sync(0xffffffffu, mx1, 1));
        mx1 = fmaxf(mx1, __shfl_xor_sync(0xffffffffu, mx1, 2));
        float nm0 = fmaxf(m0, mx0), nm1 = fmaxf(m1, mx1);
        float cr0 = __expf(m0 - nm0), cr1 = __expf(m1 - nm1);
        m0 = nm0; m1 = nm1;
        l0 *= cr0; l1 *= cr1;
#pragma unroll
        for (int n = 0; n < 4; n++) {
            o[n][0] *= cr0; o[n][1] *= cr0; o[n][2] *= cr1; o[n][3] *= cr1;
        }

        // P = exp(S - m) packed into PV A-fragments
        uint32_t pa[2][4];
        float sm0 = 0.f, sm1 = 0.f;
#pragma unroll
        for (int n = 0; n < 4; n++) {
            float p0 = __expf(s[n][0] - m0), p1 = __expf(s[n][1] - m0);
            float p2 = __expf(s[n][2] - m1), p3 = __expf(s[n][3] - m1);
            sm0 += p0 + p1; sm1 += p2 + p3;
            int j = n >> 1;
            if ((n & 1) == 0) { pa[j][0] = pkhf(p0, p1); pa[j][1] = pkhf(p2, p3); }
            else              { pa[j][2] = pkhf(p0, p1); pa[j][3] = pkhf(p2, p3); }
        }
        l0 += sm0; l1 += sm1;

        // O += P V
#pragma unroll
        for (int j = 0; j < 2; j++)
#pragma unroll
            for (int nn = 0; nn < 4; nn++) {
                uint32_t b0, b1;
                ldsm_x2_t(b0, b1, Vb + (16 * j + (lane & 15)) * KROW + nn * 16);
                mma_f16(o[nn], pa[j], b0, b1);
            }
        __syncthreads();
    }

    // reduce row sums across quad
    l0 += __shfl_xor_sync(0xffffffffu, l0, 1);
    l0 += __shfl_xor_sync(0xffffffffu, l0, 2);
    l1 += __shfl_xor_sync(0xffffffffu, l1, 1);
    l1 += __shfl_xor_sync(0xffffffffu, l1, 2);

    // store split-K partials
    const int qr = q0 + qh * 16 + rq;
    const size_t i0 = ((size_t)(sp * Qn + qr) * Hh + w) * CH;
    const size_t i1 = ((size_t)(sp * Qn + qr + 8) * Hh + w) * CH;
#pragma unroll
    for (int nn = 0; nn < 4; nn++) {
        *(float2*)(g_pacc + i0 + nn * 8 + c2) = make_float2(o[nn][0], o[nn][1]);
        *(float2*)(g_pacc + i1 + nn * 8 + c2) = make_float2(o[nn][2], o[nn][3]);
    }
    if ((lane & 3) == 0) {
        g_pm[(size_t)(sp * Qn + qr) * Hh + w] = m0;
        g_pl[(size_t)(sp * Qn + qr) * Hh + w] = l0;
        g_pm[(size_t)(sp * Qn + qr + 8) * Hh + w] = m1;
        g_pl[(size_t)(sp * Qn + qr + 8) * Hh + w] = l1;
    }
}

// ---------------- kernel 3: split-K merge, thread per (q,h,c4) ------------------------
__global__ __launch_bounds__(256) void merge_kernel() {
    const int idx = blockIdx.x * 256 + threadIdx.x;   // 0 .. Qn*Hh*8-1
    const int c4 = idx & 7;
    const int h  = (idx >> 3) & 7;
    const int q  = idx >> 6;
    const int ih = q * Hh + h;

    float mj[SPLITK], lj[SPLITK];
    float M = -__int_as_float(0x7f800000);
#pragma unroll
    for (int j = 0; j < SPLITK; j++) {
        mj[j] = g_pm[j * Qn * Hh + ih];
        lj[j] = g_pl[j * Qn * Hh + ih];
        M = fmaxf(M, mj[j]);
    }
    float wj[SPLITK], L = 0.f;
#pragma unroll
    for (int j = 0; j < SPLITK; j++) {
        wj[j] = __expf(mj[j] - M);
        L += wj[j] * lj[j];
    }
    const float inv = 1.f / L;

    float4 a = make_float4(0.f, 0.f, 0.f, 0.f);
#pragma unroll
    for (int j = 0; j < SPLITK; j++) {
        const float4 pj = ((const float4*)g_pacc)[(size_t)(j * Qn * Hh + ih) * 8 + c4];
        a.x += wj[j] * pj.x; a.y += wj[j] * pj.y;
        a.z += wj[j] * pj.z; a.w += wj[j] * pj.w;
    }
    const float4 g = *(const float4*)(g_g + (size_t)q * HD + h * CH + c4 * 4);
    a.x *= inv * g.x; a.y *= inv * g.y; a.z *= inv * g.z; a.w *= inv * g.w;

    __half2 h0 = __floats2half2_rn(a.x, a.y);
    __half2 h1 = __floats2half2_rn(a.z, a.w);
    __half2 lo0 = __floats2half2_rn(a.x - __half2float(h0.x),
                                    a.y - __half2float(h0.y));
    __half2 lo1 = __floats2half2_rn(a.z - __half2float(h1.x),
                                    a.w - __half2float(h1.y));
    __half* ph = g_ohi + (size_t)q * HD + h * CH + c4 * 4;
    __half* pl = g_olo + (size_t)q * HD + h * CH + c4 * 4;
    *(__half2*)ph = h0;       *(__half2*)(ph + 2) = h1;
    *(__half2*)pl = lo0;      *(__half2*)(pl + 2) = lo1;
}

// ---------------- kernel 4: output projection via HMMA (hi/lo compensated) ------------
__global__ __launch_bounds__(256) void out_h(const float* __restrict__ bo,
                                             float* __restrict__ out) {
    extern __shared__ char sm[];
    const int tid = threadIdx.x, w = tid >> 5, lane = tid & 31;
    const int bm = blockIdx.x, bn = blockIdx.y;
    const int wm = w & 1, wn = w >> 1;
    const uint32_t sb = smem_u32(sm);

    auto stage = [&](int t, int buf) {
        const __half* arr = (t < 4) ? g_ohi : g_olo;
        const int colbase = (t & 1) * 128;
        const uint32_t ab = sb + buf * OBUF;
        const uint32_t bb = ab + OA_BYTES;
#pragma unroll
        for (int r = 0; r < 2; r++) {
            int idx = tid + 256 * r;
            int row = idx >> 4, c = idx & 15;
            cpasync16(ab + (row * OA_PITCH + c * 8) * 2,
                      arr + (size_t)(bm * 32 + row) * HD + colbase + c * 8);
        }
#pragma unroll
        for (int r = 0; r < 4; r++) {
            int idx = tid + 256 * r;
            int row = idx >> 3, c = idx & 7;
            cpasync16(bb + (row * OB_PITCH + c * 8) * 2,
                      g_w2 + (size_t)(t * 128 + row) * Cin + bn * 64 + c * 8);
        }
        cp_commit();
    };

    float c[2][4];
#pragma unroll
    for (int n = 0; n < 2; n++)
#pragma unroll
        for (int j = 0; j < 4; j++) c[n][j] = 0.f;

    stage(0, 0);
    for (int t = 0; t < 6; t++) {
        const int b = t & 1;
        if (t + 1 < 6) { stage(t + 1, b ^ 1); cp_wait<1>(); }
        else           { cp_wait<0>(); }
        __syncthreads();

        const uint32_t ab = sb + b * OBUF;
        const uint32_t bb = ab + OA_BYTES;
        const uint32_t Ab = ab +
            (((16 * wm + ((lane >> 3) & 1) * 8 + (lane & 7)) * OA_PITCH) + ((lane >> 4) & 1) * 8) * 2;
        const uint32_t Bb = bb + ((lane & 15) * OB_PITCH + wn * 16) * 2;

#pragma unroll
        for (int ks = 0; ks < 8; ks++) {
            uint32_t a[4];
            ldsm_x4(a, Ab + ks * 32);
#pragma unroll
            for (int nf = 0; nf < 2; nf++) {
                uint32_t b0, b1;
                ldsm_x2_t(b0, b1, Bb + (ks * 16 * OB_PITCH + nf * 8) * 2);
                mma_f16(c[nf], a, b0, b1);
            }
        }
        __syncthreads();
    }

    const int rq = lane >> 2, c2 = (lane & 3) * 2;
    const int row = bm * 32 + 16 * wm + rq;
#pragma unroll
    for (int nf = 0; nf < 2; nf++) {
        int col = bn * 64 + wn * 16 + nf * 8 + c2;
        float b0 = bo[col], b1 = bo[col + 1];
        *(float2*)(out + (size_t)row * Cin + col) =
            make_float2(c[nf][0] + b0, c[nf][1] + b1);
        *(float2*)(out + (size_t)(row + 8) * Cin + col) =
            make_float2(c[nf][2] + b0, c[nf][3] + b1);
    }
}

// ---------------- launch --------------------------------------------------------------
extern "C" void kernel_launch(void* const* d_in, const int* in_sizes, int n_in,
                              void* d_out, int out_size) {
    (void)in_sizes; (void)n_in; (void)out_size;
    const float* qx   = (const float*)d_in[0];
    const float* kvx  = (const float*)d_in[1];
    const float* bias = (const float*)d_in[2];
    const float* dist = (const float*)d_in[3];
    const float* Wq   = (const float*)d_in[4];
    const float* Wk   = (const float*)d_in[5];
    const float* Wv   = (const float*)d_in[6];
    const float* Wg   = (const float*)d_in[7];
    const float* bg   = (const float*)d_in[8];
    const float* Wo   = (const float*)d_in[9];
    const float* bo   = (const float*)d_in[10];
    float* out = (float*)d_out;

    cudaFuncSetAttribute(attn_kernel, cudaFuncAttributeMaxDynamicSharedMemorySize, SM_BYTES);
    cudaFuncSetAttribute(proj_h,      cudaFuncAttributeMaxDynamicSharedMemorySize, PJ_SMEM);
    cudaFuncSetAttribute(out_h,       cudaFuncAttributeMaxDynamicSharedMemorySize, OUT_SMEM);

    convert_kernel<<<dim3(32, 7), 256>>>(qx, kvx, Wq, Wk, Wv, Wg, Wo);
    proj_h<<<dim3(Qn / 128, HD / 64, 4), 256, PJ_SMEM>>>(bg);
    attn_kernel<<<dim3(Qn / TQ, SPLITK), 512, SM_BYTES>>>(bias, dist);
    merge_kernel<<<dim3(Qn * Hh * 8 / 256), 256>>>();
    out_h<<<dim3(Qn / 32, Cin / 64), 256, OUT_SMEM>>>(bo, out);
}